// round 13
// baseline (speedup 1.0000x reference)
#include <cuda_runtime.h>
#include <cuda_bf16.h>
#include <math.h>
#include <stdint.h>

// Problem constants (fixed shapes)
#define BB 2
#define QQ 1568
#define CC 768
#define HH 12
#define DD 64
#define FF 8
#define SS 196
#define M1 (BB*QQ)              // 3136 flattened rows
#define QOUT_ELEMS (BB*QQ*CC)   // 2408448
#define QTILES 13               // ceil(1568/128)

// ---------------- scratch (device globals: allocation-free rule) -------------
__device__ float          g_q    [M1*CC];
__device__ float          g_kv   [M1*2*CC];
__device__ float          g_q2   [M1*CC];
__device__ __nv_bfloat16  g_m    [M1*HH*CC];
__device__ __nv_bfloat16  g_x    [BB*QQ*FF*CC];     // bf16: halves x traffic
__device__ float          g_xp2  [QTILES*BB*FF*CC];
__device__ float          g_xsum [BB*FF*CC];
__device__ float          g_v2   [BB*FF*CC];
__device__ float          g_y    [M1*CC];

namespace {
struct ModulePreload {
    ModulePreload() {
        void* p = nullptr;
        cudaGetSymbolAddress(&p, g_q);
    }
};
static ModulePreload _module_preload;
}

// ---------------- tf32 helpers ----------------------------------------------
__device__ __forceinline__ unsigned f2tf(float x) {
    unsigned r;
    asm("cvt.rna.tf32.f32 %0, %1;" : "=r"(r) : "f"(x));
    return r;
}
__device__ __forceinline__ void cvt_hilo4(float4 v, uint4& h, uint4& l) {
    h.x = f2tf(v.x); h.y = f2tf(v.y); h.z = f2tf(v.z); h.w = f2tf(v.w);
    l.x = f2tf(v.x - __uint_as_float(h.x));
    l.y = f2tf(v.y - __uint_as_float(h.y));
    l.z = f2tf(v.z - __uint_as_float(h.z));
    l.w = f2tf(v.w - __uint_as_float(h.w));
}
__device__ __forceinline__ uint4 cvt_tf4(float4 v) {
    uint4 h;
    h.x = f2tf(v.x); h.y = f2tf(v.y); h.z = f2tf(v.z); h.w = f2tf(v.w);
    return h;
}
#define MMA_TF32(d, a, b)                                                     \
    asm volatile(                                                             \
        "mma.sync.aligned.m16n8k8.row.col.f32.tf32.tf32.f32 "                 \
        "{%0,%1,%2,%3}, {%4,%5,%6,%7}, {%8,%9}, {%0,%1,%2,%3};"               \
        : "+f"((d)[0]), "+f"((d)[1]), "+f"((d)[2]), "+f"((d)[3])              \
        : "r"((a)[0]), "r"((a)[1]), "r"((a)[2]), "r"((a)[3]),                 \
          "r"((b)[0]), "r"((b)[1]))

// ---------------- split-tf32 128x128 GEMM (NN), register-prefetch -----------
// Columns < n_full use 3-term split emulation; columns >= n_full single tf32
// (for consumers that can't see the extra precision anyway).
__global__ void sgemm_tf32_nn(const float* __restrict__ A, const float* __restrict__ B,
                              float* __restrict__ C, int M, int K,
                              int lda, int ldb, int ldc,
                              float alpha, const float* __restrict__ bias, int n_full)
{
    extern __shared__ unsigned smu[];
    unsigned* AsH = smu;             // [128][36]
    unsigned* AsL = AsH + 4608;
    unsigned* BsH = AsL + 4608;      // [32][132]
    unsigned* BsL = BsH + 4224;

    int tid = threadIdx.x;
    int lane = tid & 31, wid = tid >> 5;
    int warp_m = wid >> 2, warp_n = wid & 3;
    int g = lane >> 2, t = lane & 3;
    int bm = blockIdx.y * 128, bn = blockIdx.x * 128;
    bool do_lo = (bn < n_full);

    const float* Ap[4];
    const float* Bp[4];
    int aoff[4], boff[4];
#pragma unroll
    for (int it = 0; it < 4; it++) {
        int idx = tid + it * 256;
        int ar = idx >> 3, ac = (idx & 7) << 2;
        int aR = bm + ar; if (aR >= M) aR = M - 1;
        Ap[it] = A + (size_t)aR * lda + ac;
        aoff[it] = ar * 36 + ac;
        int bk = idx >> 5, bn0 = (idx & 31) << 2;
        Bp[it] = B + (size_t)bk * ldb + bn + bn0;
        boff[it] = bk * 132 + bn0;
    }

    float4 aR4[4], bR4[4];
#pragma unroll
    for (int it = 0; it < 4; it++) {
        aR4[it] = *(const float4*)(Ap[it]);
        bR4[it] = *(const float4*)(Bp[it]);
    }

    float acc[4][4][4] = {};
    int nkt = K >> 5;
    for (int kt = 0; kt < nkt; kt++) {
#pragma unroll
        for (int it = 0; it < 4; it++) {
            uint4 h, l;
            cvt_hilo4(aR4[it], h, l);
            *(uint4*)&AsH[aoff[it]] = h;
            *(uint4*)&AsL[aoff[it]] = l;
            cvt_hilo4(bR4[it], h, l);
            *(uint4*)&BsH[boff[it]] = h;
            *(uint4*)&BsL[boff[it]] = l;
        }
        __syncthreads();
        if (kt + 1 < nkt) {
#pragma unroll
            for (int it = 0; it < 4; it++) {
                aR4[it] = *(const float4*)(Ap[it] + (kt + 1) * 32);
                bR4[it] = *(const float4*)(Bp[it] + (size_t)(kt + 1) * 32 * ldb);
            }
        }
#pragma unroll
        for (int ks = 0; ks < 4; ks++) {
            int kb = ks * 8 + t;
            unsigned bh[4][2], bl[4][2];
#pragma unroll
            for (int j = 0; j < 4; j++) {
                int n = warp_n * 32 + j * 8 + g;
                bh[j][0] = BsH[kb * 132 + n];
                bh[j][1] = BsH[(kb + 4) * 132 + n];
                bl[j][0] = BsL[kb * 132 + n];
                bl[j][1] = BsL[(kb + 4) * 132 + n];
            }
#pragma unroll
            for (int i = 0; i < 4; i++) {
                int m = warp_m * 64 + i * 16 + g;
                unsigned ah[4], al[4];
                ah[0] = AsH[m * 36 + kb];
                ah[1] = AsH[(m + 8) * 36 + kb];
                ah[2] = AsH[m * 36 + kb + 4];
                ah[3] = AsH[(m + 8) * 36 + kb + 4];
                al[0] = AsL[m * 36 + kb];
                al[1] = AsL[(m + 8) * 36 + kb];
                al[2] = AsL[m * 36 + kb + 4];
                al[3] = AsL[(m + 8) * 36 + kb + 4];
#pragma unroll
                for (int j = 0; j < 4; j++) {
                    MMA_TF32(acc[i][j], ah, bh[j]);
                    if (do_lo) {
                        MMA_TF32(acc[i][j], ah, bl[j]);
                        MMA_TF32(acc[i][j], al, bh[j]);
                    }
                }
            }
        }
        __syncthreads();
    }

#pragma unroll
    for (int i = 0; i < 4; i++) {
#pragma unroll
        for (int j = 0; j < 4; j++) {
            int r0 = bm + warp_m * 64 + i * 16 + g;
            int c0 = bn + warp_n * 32 + j * 8 + 2 * t;
            float2 v0, v1;
            v0.x = alpha * acc[i][j][0]; v0.y = alpha * acc[i][j][1];
            v1.x = alpha * acc[i][j][2]; v1.y = alpha * acc[i][j][3];
            if (bias) {
                float bx = bias[c0], by = bias[c0 + 1];
                v0.x += bx; v0.y += by; v1.x += bx; v1.y += by;
            }
            if (r0 < M)     *(float2*)&C[(size_t)r0 * ldc + c0] = v0;
            if (r0 + 8 < M) *(float2*)&C[(size_t)(r0 + 8) * ldc + c0] = v1;
        }
    }
}

// ---------------- single-tf32 batched NT GEMM for m (bf16 out) ---------------
__global__ void __launch_bounds__(256, 2)
gemm_m_tf32(const float* __restrict__ q2, const float* __restrict__ Wpkv,
            __nv_bfloat16* __restrict__ mOut)
{
    extern __shared__ unsigned smu[];
    unsigned* As = smu;              // [128][36]
    unsigned* Bs = smu + 4608;       // [128n][36]

    int h = blockIdx.z;
    const float* A  = q2   + h * 64;                  // lda 768
    const float* BT = Wpkv + h * 64;                  // ld 1536
    __nv_bfloat16* Cb = mOut + h * 768;               // ldc 9216

    int tid = threadIdx.x;
    int lane = tid & 31, wid = tid >> 5;
    int warp_m = wid >> 2, warp_n = wid & 3;
    int g = lane >> 2, t = lane & 3;
    int bm = blockIdx.y * 128, bn = blockIdx.x * 128;

    int r0t = tid >> 3, c0t = (tid & 7) << 2;

    float4 aPre[4], bPre[4];
#pragma unroll
    for (int it = 0; it < 4; it++) {
        int aR2 = bm + r0t + it * 32; if (aR2 >= M1) aR2 = M1 - 1;
        aPre[it] = *(const float4*)(A + (size_t)aR2 * 768 + c0t);
        bPre[it] = *(const float4*)(BT + (size_t)(bn + r0t + it * 32) * 1536 + c0t);
    }

    float acc[4][4][4] = {};
#pragma unroll 1
    for (int kt = 0; kt < 2; kt++) {                  // K = 64 = 2 x 32
#pragma unroll
        for (int it = 0; it < 4; it++) {
            int r = r0t + it * 32;
            *(uint4*)&As[r * 36 + c0t] = cvt_tf4(aPre[it]);
            *(uint4*)&Bs[r * 36 + c0t] = cvt_tf4(bPre[it]);
        }
        __syncthreads();
        if (kt == 0) {
#pragma unroll
            for (int it = 0; it < 4; it++) {
                int aR2 = bm + r0t + it * 32; if (aR2 >= M1) aR2 = M1 - 1;
                aPre[it] = *(const float4*)(A + (size_t)aR2 * 768 + 32 + c0t);
                bPre[it] = *(const float4*)(BT + (size_t)(bn + r0t + it * 32) * 1536 + 32 + c0t);
            }
        }
#pragma unroll
        for (int ks = 0; ks < 4; ks++) {
            int kb = ks * 8 + t;
            unsigned bh[4][2];
#pragma unroll
            for (int j = 0; j < 4; j++) {
                int n = warp_n * 32 + j * 8 + g;
                bh[j][0] = Bs[n * 36 + kb];
                bh[j][1] = Bs[n * 36 + kb + 4];
            }
#pragma unroll
            for (int i = 0; i < 4; i++) {
                int m = warp_m * 64 + i * 16 + g;
                unsigned ah[4];
                ah[0] = As[m * 36 + kb];
                ah[1] = As[(m + 8) * 36 + kb];
                ah[2] = As[m * 36 + kb + 4];
                ah[3] = As[(m + 8) * 36 + kb + 4];
#pragma unroll
                for (int j = 0; j < 4; j++)
                    MMA_TF32(acc[i][j], ah, bh[j]);
            }
        }
        __syncthreads();
    }

#pragma unroll
    for (int i = 0; i < 4; i++) {
#pragma unroll
        for (int j = 0; j < 4; j++) {
            int r0 = bm + warp_m * 64 + i * 16 + g;
            int c0 = bn + warp_n * 32 + j * 8 + 2 * t;
            __nv_bfloat162 v0, v1;
            v0.x = __float2bfloat16(acc[i][j][0]);
            v0.y = __float2bfloat16(acc[i][j][1]);
            v1.x = __float2bfloat16(acc[i][j][2]);
            v1.y = __float2bfloat16(acc[i][j][3]);
            if (r0 < M1)
                *(__nv_bfloat162*)&Cb[(size_t)r0 * 9216 + c0] = v0;
            if (r0 + 8 < M1)
                *(__nv_bfloat162*)&Cb[(size_t)(r0 + 8) * 9216 + c0] = v1;
        }
    }
}

// ---------------- stage-1 fused attention, tensor-core version ---------------
__global__ void stage1_tf32(const float* __restrict__ qmat, const float* __restrict__ kv,
                            float* __restrict__ scores_out, __nv_bfloat16* __restrict__ x_out,
                            float* __restrict__ xpart)
{
    extern __shared__ unsigned smu[];
    unsigned* QsH = smu;
    unsigned* QsL = smu + 8704;
    unsigned* KsH = smu + 17408;
    unsigned* KsL = smu + 32640;
    unsigned* Ps  = smu;
    unsigned* Vs  = smu + 29184;
    float* red    = (float*)(smu + 47872);
    float* sxs    = (float*)(smu + 48384);

    int tid = threadIdx.x;
    int lane = tid & 31, wid = tid >> 5;
    int warp_m = wid >> 2, warp_n = wid & 3;   // 2m x 4n
    int g = lane >> 2, t = lane & 3;

    int q0  = blockIdx.x * 128;
    int f   = blockIdx.y;
    int bhz = blockIdx.z;
    int b = bhz / HH, h = bhz % HH;

    // ---- load Q (hi/lo tf32) ----
    const float* qbase = qmat + (size_t)(b * QQ) * CC + h * 64;
#pragma unroll
    for (int it = 0; it < 8; it++) {
        int idx = tid + it * 256;
        int row = idx >> 4, c4 = (idx & 15) << 2;
        int qg = q0 + row; if (qg >= QQ) qg = QQ - 1;
        float4 v = *(const float4*)(qbase + (size_t)qg * CC + c4);
        uint4 hh, ll; cvt_hilo4(v, hh, ll);
        *(uint4*)&QsH[row * 68 + c4] = hh;
        *(uint4*)&QsL[row * 68 + c4] = ll;
    }
    // ---- load K (hi/lo tf32), zero pad rows 196..223 ----
    const float* kbase = kv + (size_t)(b * QQ + f * SS) * (2 * CC) + h * 64;
#pragma unroll
    for (int it = 0; it < 14; it++) {
        int idx = tid + it * 256;
        int s = idx >> 4, c4 = (idx & 15) << 2;
        float4 v = make_float4(0.f, 0.f, 0.f, 0.f);
        if (s < SS) v = *(const float4*)(kbase + (size_t)s * (2 * CC) + c4);
        uint4 hh, ll; cvt_hilo4(v, hh, ll);
        *(uint4*)&KsH[s * 68 + c4] = hh;
        *(uint4*)&KsL[s * 68 + c4] = ll;
    }
    __syncthreads();

    // ---- QK^T mma: warp tile 64m x 56n, K=64 in 8 steps, 3 terms ----
    float acc[4][7][4] = {};
#pragma unroll 1
    for (int ks = 0; ks < 8; ks++) {
        int kb = ks * 8 + t;
        unsigned bh[7][2], bl[7][2];
#pragma unroll
        for (int j = 0; j < 7; j++) {
            int n = (warp_n * 7 + j) * 8 + g;
            bh[j][0] = KsH[n * 68 + kb];
            bh[j][1] = KsH[n * 68 + kb + 4];
            bl[j][0] = KsL[n * 68 + kb];
            bl[j][1] = KsL[n * 68 + kb + 4];
        }
#pragma unroll
        for (int i = 0; i < 4; i++) {
            int m = warp_m * 64 + i * 16 + g;
            unsigned ah[4], al[4];
            ah[0] = QsH[m * 68 + kb];
            ah[1] = QsH[(m + 8) * 68 + kb];
            ah[2] = QsH[m * 68 + kb + 4];
            ah[3] = QsH[(m + 8) * 68 + kb + 4];
            al[0] = QsL[m * 68 + kb];
            al[1] = QsL[(m + 8) * 68 + kb];
            al[2] = QsL[m * 68 + kb + 4];
            al[3] = QsL[(m + 8) * 68 + kb + 4];
#pragma unroll
            for (int j = 0; j < 7; j++) {
                MMA_TF32(acc[i][j], ah, bh[j]);
                MMA_TF32(acc[i][j], ah, bl[j]);
                MMA_TF32(acc[i][j], al, bh[j]);
            }
        }
    }
    __syncthreads();   // Q/K smem dead; phase B regions may now be written

    // ---- load V transposed to Vs[d][s] (single tf32), zero pad s ----
    const float* vbase = kbase + CC;
#pragma unroll
    for (int it = 0; it < 14; it++) {
        int idx = tid + it * 256;
        int d = idx & 63, sg = idx >> 6;   // sg 0..55
        int s0 = sg * 4;
        uint4 w;
        w.x = (s0 + 0 < SS) ? f2tf(vbase[(size_t)(s0 + 0) * (2 * CC) + d]) : 0u;
        w.y = (s0 + 1 < SS) ? f2tf(vbase[(size_t)(s0 + 1) * (2 * CC) + d]) : 0u;
        w.z = (s0 + 2 < SS) ? f2tf(vbase[(size_t)(s0 + 2) * (2 * CC) + d]) : 0u;
        w.w = (s0 + 3 < SS) ? f2tf(vbase[(size_t)(s0 + 3) * (2 * CC) + d]) : 0u;
        *(uint4*)&Vs[d * 228 + s0] = w;
    }

    // ---- scale + write raw scores ----
    const float scale = 0.125f;
#pragma unroll
    for (int i = 0; i < 4; i++) {
        int r0 = warp_m * 64 + i * 16 + g;
#pragma unroll
        for (int j = 0; j < 7; j++) {
            int col = (warp_n * 7 + j) * 8 + 2 * t;
#pragma unroll
            for (int c = 0; c < 4; c++) acc[i][j][c] *= scale;
            if (col < SS) {
                int qa = q0 + r0;
                if (qa < QQ) {
                    size_t bp = ((size_t)bhz * QQ + qa) * (FF * SS) + (size_t)f * SS + col;
                    *(float2*)&scores_out[bp] = make_float2(acc[i][j][0], acc[i][j][1]);
                }
                int qb2 = q0 + r0 + 8;
                if (qb2 < QQ) {
                    size_t bp = ((size_t)bhz * QQ + qb2) * (FF * SS) + (size_t)f * SS + col;
                    *(float2*)&scores_out[bp] = make_float2(acc[i][j][2], acc[i][j][3]);
                }
            }
        }
    }

    // ---- softmax over s (row-wise) ----
    float mxa[4], mxb[4];
#pragma unroll
    for (int i = 0; i < 4; i++) {
        float m0 = -1e30f, m1 = -1e30f;
#pragma unroll
        for (int j = 0; j < 7; j++) {
            int col = (warp_n * 7 + j) * 8 + 2 * t;
            if (col < SS) {
                m0 = fmaxf(m0, fmaxf(acc[i][j][0], acc[i][j][1]));
                m1 = fmaxf(m1, fmaxf(acc[i][j][2], acc[i][j][3]));
            }
        }
        m0 = fmaxf(m0, __shfl_xor_sync(0xffffffffu, m0, 1));
        m0 = fmaxf(m0, __shfl_xor_sync(0xffffffffu, m0, 2));
        m1 = fmaxf(m1, __shfl_xor_sync(0xffffffffu, m1, 1));
        m1 = fmaxf(m1, __shfl_xor_sync(0xffffffffu, m1, 2));
        int r0 = warp_m * 64 + i * 16 + g;
        if (t == 0) {
            red[r0 * 4 + warp_n] = m0;
            red[(r0 + 8) * 4 + warp_n] = m1;
        }
    }
    __syncthreads();
#pragma unroll
    for (int i = 0; i < 4; i++) {
        int r0 = warp_m * 64 + i * 16 + g;
        mxa[i] = fmaxf(fmaxf(red[r0 * 4], red[r0 * 4 + 1]),
                       fmaxf(red[r0 * 4 + 2], red[r0 * 4 + 3]));
        mxb[i] = fmaxf(fmaxf(red[(r0 + 8) * 4], red[(r0 + 8) * 4 + 1]),
                       fmaxf(red[(r0 + 8) * 4 + 2], red[(r0 + 8) * 4 + 3]));
    }
    __syncthreads();
#pragma unroll
    for (int i = 0; i < 4; i++) {
        float s0 = 0.f, s1 = 0.f;
#pragma unroll
        for (int j = 0; j < 7; j++) {
            int col = (warp_n * 7 + j) * 8 + 2 * t;
            if (col < SS) {
                acc[i][j][0] = __expf(acc[i][j][0] - mxa[i]);
                acc[i][j][1] = __expf(acc[i][j][1] - mxa[i]);
                acc[i][j][2] = __expf(acc[i][j][2] - mxb[i]);
                acc[i][j][3] = __expf(acc[i][j][3] - mxb[i]);
                s0 += acc[i][j][0] + acc[i][j][1];
                s1 += acc[i][j][2] + acc[i][j][3];
            } else {
                acc[i][j][0] = acc[i][j][1] = acc[i][j][2] = acc[i][j][3] = 0.f;
            }
        }
        s0 += __shfl_xor_sync(0xffffffffu, s0, 1);
        s0 += __shfl_xor_sync(0xffffffffu, s0, 2);
        s1 += __shfl_xor_sync(0xffffffffu, s1, 1);
        s1 += __shfl_xor_sync(0xffffffffu, s1, 2);
        int r0 = warp_m * 64 + i * 16 + g;
        if (t == 0) {
            red[r0 * 4 + warp_n] = s0;
            red[(r0 + 8) * 4 + warp_n] = s1;
        }
    }
    __syncthreads();
#pragma unroll
    for (int i = 0; i < 4; i++) {
        int r0 = warp_m * 64 + i * 16 + g;
        float inva = 1.0f / (red[r0 * 4] + red[r0 * 4 + 1] + red[r0 * 4 + 2] + red[r0 * 4 + 3]);
        float invb = 1.0f / (red[(r0 + 8) * 4] + red[(r0 + 8) * 4 + 1] +
                             red[(r0 + 8) * 4 + 2] + red[(r0 + 8) * 4 + 3]);
#pragma unroll
        for (int j = 0; j < 7; j++) {
            int col = (warp_n * 7 + j) * 8 + 2 * t;
            Ps[r0 * 228 + col]           = f2tf(acc[i][j][0] * inva);
            Ps[r0 * 228 + col + 1]       = f2tf(acc[i][j][1] * inva);
            Ps[(r0 + 8) * 228 + col]     = f2tf(acc[i][j][2] * invb);
            Ps[(r0 + 8) * 228 + col + 1] = f2tf(acc[i][j][3] * invb);
        }
    }
    __syncthreads();

    // ---- x = P @ V: warp tile 64m x 16n, K=224 in 28 steps, single term ----
    float xacc[4][2][4] = {};
#pragma unroll 1
    for (int ks = 0; ks < 28; ks++) {
        int kb = ks * 8 + t;
        unsigned bf[2][2];
#pragma unroll
        for (int j = 0; j < 2; j++) {
            int n = warp_n * 16 + j * 8 + g;
            bf[j][0] = Vs[n * 228 + kb];
            bf[j][1] = Vs[n * 228 + kb + 4];
        }
#pragma unroll
        for (int i = 0; i < 4; i++) {
            int m = warp_m * 64 + i * 16 + g;
            unsigned a[4];
            a[0] = Ps[m * 228 + kb];
            a[1] = Ps[(m + 8) * 228 + kb];
            a[2] = Ps[m * 228 + kb + 4];
            a[3] = Ps[(m + 8) * 228 + kb + 4];
#pragma unroll
            for (int j = 0; j < 2; j++)
                MMA_TF32(xacc[i][j], a, bf[j]);
        }
    }

    // ---- write x (bf16) + fp32 column sums over this q-tile ----
    float cs[2][2] = {};
#pragma unroll
    for (int i = 0; i < 4; i++) {
        int r0 = warp_m * 64 + i * 16 + g;
        bool va = (q0 + r0) < QQ;
        bool vb = (q0 + r0 + 8) < QQ;
#pragma unroll
        for (int j = 0; j < 2; j++) {
            int c = h * 64 + warp_n * 16 + j * 8 + 2 * t;
            if (va) {
                __nv_bfloat162 w;
                w.x = __float2bfloat16(xacc[i][j][0]);
                w.y = __float2bfloat16(xacc[i][j][1]);
                *(__nv_bfloat162*)&x_out[((size_t)(b * QQ + q0 + r0) * FF + f) * CC + c] = w;
                cs[j][0] += xacc[i][j][0];
                cs[j][1] += xacc[i][j][1];
            }
            if (vb) {
                __nv_bfloat162 w;
                w.x = __float2bfloat16(xacc[i][j][2]);
                w.y = __float2bfloat16(xacc[i][j][3]);
                *(__nv_bfloat162*)&x_out[((size_t)(b * QQ + q0 + r0 + 8) * FF + f) * CC + c] = w;
                cs[j][0] += xacc[i][j][2];
                cs[j][1] += xacc[i][j][3];
            }
        }
    }
#pragma unroll
    for (int off = 4; off < 32; off <<= 1) {
#pragma unroll
        for (int j = 0; j < 2; j++) {
            cs[j][0] += __shfl_down_sync(0xffffffffu, cs[j][0], off);
            cs[j][1] += __shfl_down_sync(0xffffffffu, cs[j][1], off);
        }
    }
    if (lane < 4) {
#pragma unroll
        for (int j = 0; j < 2; j++) {
            sxs[warp_m * 64 + warp_n * 16 + j * 8 + 2 * t]     = cs[j][0];
            sxs[warp_m * 64 + warp_n * 16 + j * 8 + 2 * t + 1] = cs[j][1];
        }
    }
    __syncthreads();
    if (tid < 64) {
        float tot = sxs[tid] + sxs[64 + tid];
        xpart[(((size_t)blockIdx.x * BB + b) * FF + f) * CC + h * 64 + tid] = tot;
    }
}

// ---------------- final xsum over 13 q-tiles ---------------------------------
__global__ void xsum_final13(const float* __restrict__ part, float* __restrict__ xsum)
{
    int c = blockIdx.x * 256 + threadIdx.x;
    int f = blockIdx.y;
    int b = blockIdx.z;
    float acc = 0.f;
#pragma unroll
    for (int qt = 0; qt < QTILES; qt++)
        acc += part[(((size_t)qt * BB + b) * FF + f) * CC + c];
    xsum[((size_t)b * FF + f) * CC + c] = acc;
}

// ---------------- V2sum = Xsum @ Wpkv_v  (tiny) ------------------------------
__global__ void v2_kernel(const float* __restrict__ xsum, const float* __restrict__ Wpkv,
                          float* __restrict__ v2)
{
    __shared__ float xs[CC];
    int bf = blockIdx.x;
    int tid = threadIdx.x;
    for (int i = tid; i < CC; i += 256) xs[i] = xsum[(size_t)bf * CC + i];
    __syncthreads();
#pragma unroll
    for (int r = 0; r < 3; r++) {
        int co = r * 256 + tid;
        float acc = 0.f;
        for (int ci = 0; ci < CC; ci++)
            acc += xs[ci] * Wpkv[(size_t)ci * (2 * CC) + CC + co];
        v2[(size_t)bf * CC + co] = acc;
    }
}

// ---------------- stage-2: attn2 softmax + y (m, x in bf16) ------------------
__global__ void stage2_kernel(const __nv_bfloat16* __restrict__ x,
                              const __nv_bfloat16* __restrict__ m,
                              const float* __restrict__ v2, float* __restrict__ y)
{
    __shared__ float xs[FF * CC];
    int bq = blockIdx.x;
    int b = bq / QQ;
    int tid = threadIdx.x;

    const __nv_bfloat16* xrow = x + (size_t)bq * (FF * CC);
    for (int idx = tid; idx < (FF * CC) / 2; idx += 384) {
        __nv_bfloat162 w = *(const __nv_bfloat162*)(xrow + ((size_t)idx << 1));
        xs[(idx << 1)]     = __bfloat162float(w.x);
        xs[(idx << 1) + 1] = __bfloat162float(w.y);
    }
    __syncthreads();

    int h = tid >> 5, lane = tid & 31;
    const __nv_bfloat16* mrow = m + (size_t)bq * (HH * CC) + (size_t)h * CC;

    float a[FF];
#pragma unroll
    for (int f2 = 0; f2 < FF; f2++) a[f2] = 0.f;
#pragma unroll 4
    for (int c = lane; c < CC; c += 32) {
        float mv = __bfloat162float(__ldg(mrow + c));
#pragma unroll
        for (int f2 = 0; f2 < FF; f2++) a[f2] += mv * xs[f2 * CC + c];
    }
#pragma unroll
    for (int f2 = 0; f2 < FF; f2++)
        for (int o = 16; o > 0; o >>= 1) a[f2] += __shfl_xor_sync(0xffffffffu, a[f2], o);

    float mx = a[0];
#pragma unroll
    for (int f2 = 1; f2 < FF; f2++) mx = fmaxf(mx, a[f2]);
    float ssum = 0.f;
#pragma unroll
    for (int f2 = 0; f2 < FF; f2++) { a[f2] = __expf(a[f2] - mx); ssum += a[f2]; }
    float inv = 1.0f / ssum;
#pragma unroll
    for (int f2 = 0; f2 < FF; f2++) a[f2] *= inv;

    for (int dd = lane; dd < 64; dd += 32) {
        float acc = 0.f;
#pragma unroll
        for (int f2 = 0; f2 < FF; f2++)
            acc += a[f2] * __ldg(v2 + ((size_t)(b * FF + f2)) * CC + h * 64 + dd);
        y[(size_t)bq * CC + h * 64 + dd] = acc;
    }
}

// ---------------- launch -----------------------------------------------------
extern "C" void kernel_launch(void* const* d_in, const int* in_sizes, int n_in,
                              void* d_out, int out_size)
{
    const float* query  = (const float*)d_in[0];
    const float* memory = (const float*)d_in[1];
    const float* Wq     = (const float*)d_in[2];
    const float* Wkv    = (const float*)d_in[3];
    const float* Wpq    = (const float*)d_in[4];
    const float* Wpkv   = (const float*)d_in[5];
    const float* Wproj  = (const float*)d_in[6];
    const float* bproj  = (const float*)d_in[7];

    float* out        = (float*)d_out;
    float* out_scores = out + QOUT_ELEMS;

    float *qp, *kvp, *q2p, *xp2p, *xsump, *v2p, *yp;
    __nv_bfloat16 *mp, *xp;
    cudaGetSymbolAddress((void**)&qp,    g_q);
    cudaGetSymbolAddress((void**)&kvp,   g_kv);
    cudaGetSymbolAddress((void**)&q2p,   g_q2);
    cudaGetSymbolAddress((void**)&mp,    g_m);
    cudaGetSymbolAddress((void**)&xp,    g_x);
    cudaGetSymbolAddress((void**)&xp2p,  g_xp2);
    cudaGetSymbolAddress((void**)&xsump, g_xsum);
    cudaGetSymbolAddress((void**)&v2p,   g_v2);
    cudaGetSymbolAddress((void**)&yp,    g_y);

    const int NN_SMEM = (4608 * 2 + 4224 * 2) * 4;   // 70656
    const int NT_SMEM = (4608 * 2) * 4;              // 36864
    const int S1_SMEM = 48512 * 4;                   // 194048
    cudaFuncSetAttribute(sgemm_tf32_nn, cudaFuncAttributeMaxDynamicSharedMemorySize, NN_SMEM);
    cudaFuncSetAttribute(gemm_m_tf32,   cudaFuncAttributeMaxDynamicSharedMemorySize, NT_SMEM);
    cudaFuncSetAttribute(stage1_tf32,   cudaFuncAttributeMaxDynamicSharedMemorySize, S1_SMEM);

    const int MB = (M1 + 127) / 128;  // 25 row-blocks

    // 1. q = query @ Wq  (full split: feeds scores)
    sgemm_tf32_nn<<<dim3(CC / 128, MB), 256, NN_SMEM>>>(query, Wq, qp, M1, CC, CC, CC, CC, 1.0f, nullptr, CC);
    // 2. kv = memory @ Wkv  (K half split, V half single — V feeds tf32 PV)
    sgemm_tf32_nn<<<dim3((2 * CC) / 128, MB), 256, NN_SMEM>>>(memory, Wkv, kvp, M1, CC, CC, 2 * CC, 2 * CC, 1.0f, nullptr, CC);
    // 3. q2 = (q @ Wpq) * d^-0.5  (single tf32 — feeds bf16 m)
    sgemm_tf32_nn<<<dim3(CC / 128, MB), 256, NN_SMEM>>>(qp, Wpq, q2p, M1, CC, CC, CC, CC, 0.125f, nullptr, 0);
    // 4. m (batched per-head NT, single tf32, bf16 out)
    gemm_m_tf32<<<dim3(CC / 128, MB, HH), 256, NT_SMEM>>>(q2p, Wpkv, mp);
    // 5. stage-1 attention (tensor cores): scores + bf16 x + fused per-tile xsum
    stage1_tf32<<<dim3(QTILES, FF, BB * HH), 256, S1_SMEM>>>(qp, kvp, out_scores, xp, xp2p);
    // 6. final xsum over q-tiles
    xsum_final13<<<dim3(CC / 256, FF, BB), 256>>>(xp2p, xsump);
    // 7. V2sum = Xsum @ Wpkv_v
    v2_kernel<<<BB * FF, 256>>>(xsump, Wpkv, v2p);
    // 8. stage-2 attention -> y
    stage2_kernel<<<M1, 384>>>(xp, mp, v2p, yp);
    // 9. q_out = y @ Wproj + bproj  (full split: output)
    sgemm_tf32_nn<<<dim3(CC / 128, MB), 256, NN_SMEM>>>(yp, Wproj, out, M1, CC, CC, CC, CC, 1.0f, bproj, CC);
}

// round 15
// speedup vs baseline: 1.0431x; 1.0431x over previous
#include <cuda_runtime.h>
#include <cuda_bf16.h>
#include <math.h>
#include <stdint.h>

// Problem constants (fixed shapes)
#define BB 2
#define QQ 1568
#define CC 768
#define HH 12
#define DD 64
#define FF 8
#define SS 196
#define M1 (BB*QQ)              // 3136 flattened rows
#define QOUT_ELEMS (BB*QQ*CC)   // 2408448
#define QTILES 13               // ceil(1568/128)
#define PVK 200                 // PV padded K (196 -> 200)
#define PST 204                 // Ps/Vs row stride (words), 204 mod 32 = 12 (conflict-free)

// ---------------- scratch (device globals: allocation-free rule) -------------
__device__ float          g_q    [M1*CC];
__device__ float          g_kv   [M1*2*CC];
__device__ float          g_q2   [M1*CC];
__device__ __nv_bfloat16  g_m    [M1*HH*CC];
__device__ float          g_x    [BB*QQ*FF*CC];
__device__ float          g_xp2  [QTILES*BB*FF*CC];
__device__ float          g_xsum [BB*FF*CC];
__device__ float          g_v2   [BB*FF*CC];
__device__ float          g_y    [M1*CC];

namespace {
struct ModulePreload {
    ModulePreload() {
        void* p = nullptr;
        cudaGetSymbolAddress(&p, g_q);
    }
};
static ModulePreload _module_preload;
}

// ---------------- tf32 helpers ----------------------------------------------
__device__ __forceinline__ unsigned f2tf(float x) {
    unsigned r;
    asm("cvt.rna.tf32.f32 %0, %1;" : "=r"(r) : "f"(x));
    return r;
}
__device__ __forceinline__ void cvt_hilo4(float4 v, uint4& h, uint4& l) {
    h.x = f2tf(v.x); h.y = f2tf(v.y); h.z = f2tf(v.z); h.w = f2tf(v.w);
    l.x = f2tf(v.x - __uint_as_float(h.x));
    l.y = f2tf(v.y - __uint_as_float(h.y));
    l.z = f2tf(v.z - __uint_as_float(h.z));
    l.w = f2tf(v.w - __uint_as_float(h.w));
}
__device__ __forceinline__ uint4 cvt_tf4(float4 v) {
    uint4 h;
    h.x = f2tf(v.x); h.y = f2tf(v.y); h.z = f2tf(v.z); h.w = f2tf(v.w);
    return h;
}
#define MMA_TF32(d, a, b)                                                     \
    asm volatile(                                                             \
        "mma.sync.aligned.m16n8k8.row.col.f32.tf32.tf32.f32 "                 \
        "{%0,%1,%2,%3}, {%4,%5,%6,%7}, {%8,%9}, {%0,%1,%2,%3};"               \
        : "+f"((d)[0]), "+f"((d)[1]), "+f"((d)[2]), "+f"((d)[3])              \
        : "r"((a)[0]), "r"((a)[1]), "r"((a)[2]), "r"((a)[3]),                 \
          "r"((b)[0]), "r"((b)[1]))

// ---------------- split-tf32 128x128 GEMM (NN), register-prefetch (R12) -----
__global__ void sgemm_tf32_nn(const float* __restrict__ A, const float* __restrict__ B,
                              float* __restrict__ C, int M, int K,
                              int lda, int ldb, int ldc,
                              float alpha, const float* __restrict__ bias)
{
    extern __shared__ unsigned smu[];
    unsigned* AsH = smu;             // [128][36]
    unsigned* AsL = AsH + 4608;
    unsigned* BsH = AsL + 4608;      // [32][132]
    unsigned* BsL = BsH + 4224;

    int tid = threadIdx.x;
    int lane = tid & 31, wid = tid >> 5;
    int warp_m = wid >> 2, warp_n = wid & 3;
    int g = lane >> 2, t = lane & 3;
    int bm = blockIdx.y * 128, bn = blockIdx.x * 128;

    const float* Ap[4];
    const float* Bp[4];
    int aoff[4], boff[4];
#pragma unroll
    for (int it = 0; it < 4; it++) {
        int idx = tid + it * 256;
        int ar = idx >> 3, ac = (idx & 7) << 2;
        int aR = bm + ar; if (aR >= M) aR = M - 1;
        Ap[it] = A + (size_t)aR * lda + ac;
        aoff[it] = ar * 36 + ac;
        int bk = idx >> 5, bn0 = (idx & 31) << 2;
        Bp[it] = B + (size_t)bk * ldb + bn + bn0;
        boff[it] = bk * 132 + bn0;
    }

    float4 aR4[4], bR4[4];
#pragma unroll
    for (int it = 0; it < 4; it++) {
        aR4[it] = *(const float4*)(Ap[it]);
        bR4[it] = *(const float4*)(Bp[it]);
    }

    float acc[4][4][4] = {};
    int nkt = K >> 5;
    for (int kt = 0; kt < nkt; kt++) {
#pragma unroll
        for (int it = 0; it < 4; it++) {
            uint4 h, l;
            cvt_hilo4(aR4[it], h, l);
            *(uint4*)&AsH[aoff[it]] = h;
            *(uint4*)&AsL[aoff[it]] = l;
            cvt_hilo4(bR4[it], h, l);
            *(uint4*)&BsH[boff[it]] = h;
            *(uint4*)&BsL[boff[it]] = l;
        }
        __syncthreads();
        if (kt + 1 < nkt) {
#pragma unroll
            for (int it = 0; it < 4; it++) {
                aR4[it] = *(const float4*)(Ap[it] + (kt + 1) * 32);
                bR4[it] = *(const float4*)(Bp[it] + (size_t)(kt + 1) * 32 * ldb);
            }
        }
#pragma unroll
        for (int ks = 0; ks < 4; ks++) {
            int kb = ks * 8 + t;
            unsigned bh[4][2], bl[4][2];
#pragma unroll
            for (int j = 0; j < 4; j++) {
                int n = warp_n * 32 + j * 8 + g;
                bh[j][0] = BsH[kb * 132 + n];
                bh[j][1] = BsH[(kb + 4) * 132 + n];
                bl[j][0] = BsL[kb * 132 + n];
                bl[j][1] = BsL[(kb + 4) * 132 + n];
            }
#pragma unroll
            for (int i = 0; i < 4; i++) {
                int m = warp_m * 64 + i * 16 + g;
                unsigned ah[4], al[4];
                ah[0] = AsH[m * 36 + kb];
                ah[1] = AsH[(m + 8) * 36 + kb];
                ah[2] = AsH[m * 36 + kb + 4];
                ah[3] = AsH[(m + 8) * 36 + kb + 4];
                al[0] = AsL[m * 36 + kb];
                al[1] = AsL[(m + 8) * 36 + kb];
                al[2] = AsL[m * 36 + kb + 4];
                al[3] = AsL[(m + 8) * 36 + kb + 4];
#pragma unroll
                for (int j = 0; j < 4; j++) {
                    MMA_TF32(acc[i][j], ah, bh[j]);
                    MMA_TF32(acc[i][j], ah, bl[j]);
                    MMA_TF32(acc[i][j], al, bh[j]);
                }
            }
        }
        __syncthreads();
    }

#pragma unroll
    for (int i = 0; i < 4; i++) {
#pragma unroll
        for (int j = 0; j < 4; j++) {
            int r0 = bm + warp_m * 64 + i * 16 + g;
            int c0 = bn + warp_n * 32 + j * 8 + 2 * t;
            float2 v0, v1;
            v0.x = alpha * acc[i][j][0]; v0.y = alpha * acc[i][j][1];
            v1.x = alpha * acc[i][j][2]; v1.y = alpha * acc[i][j][3];
            if (bias) {
                float bx = bias[c0], by = bias[c0 + 1];
                v0.x += bx; v0.y += by; v1.x += bx; v1.y += by;
            }
            if (r0 < M)     *(float2*)&C[(size_t)r0 * ldc + c0] = v0;
            if (r0 + 8 < M) *(float2*)&C[(size_t)(r0 + 8) * ldc + c0] = v1;
        }
    }
}

// ---------------- single-pass tf32 128x128 GEMM (NN) -------------------------
// For products whose consumer is bf16-precision (q2 -> m). Half smem, 1/3 mma.
__global__ void sgemm_tf32_nn_1t(const float* __restrict__ A, const float* __restrict__ B,
                                 float* __restrict__ C, int M, int K,
                                 int lda, int ldb, int ldc, float alpha)
{
    extern __shared__ unsigned smu[];
    unsigned* AsH = smu;             // [128][36]
    unsigned* BsH = smu + 4608;      // [32][132]

    int tid = threadIdx.x;
    int lane = tid & 31, wid = tid >> 5;
    int warp_m = wid >> 2, warp_n = wid & 3;
    int g = lane >> 2, t = lane & 3;
    int bm = blockIdx.y * 128, bn = blockIdx.x * 128;

    const float* Ap[4];
    const float* Bp[4];
    int aoff[4], boff[4];
#pragma unroll
    for (int it = 0; it < 4; it++) {
        int idx = tid + it * 256;
        int ar = idx >> 3, ac = (idx & 7) << 2;
        int aR = bm + ar; if (aR >= M) aR = M - 1;
        Ap[it] = A + (size_t)aR * lda + ac;
        aoff[it] = ar * 36 + ac;
        int bk = idx >> 5, bn0 = (idx & 31) << 2;
        Bp[it] = B + (size_t)bk * ldb + bn + bn0;
        boff[it] = bk * 132 + bn0;
    }

    float4 aR4[4], bR4[4];
#pragma unroll
    for (int it = 0; it < 4; it++) {
        aR4[it] = *(const float4*)(Ap[it]);
        bR4[it] = *(const float4*)(Bp[it]);
    }

    float acc[4][4][4] = {};
    int nkt = K >> 5;
    for (int kt = 0; kt < nkt; kt++) {
#pragma unroll
        for (int it = 0; it < 4; it++) {
            *(uint4*)&AsH[aoff[it]] = cvt_tf4(aR4[it]);
            *(uint4*)&BsH[boff[it]] = cvt_tf4(bR4[it]);
        }
        __syncthreads();
        if (kt + 1 < nkt) {
#pragma unroll
            for (int it = 0; it < 4; it++) {
                aR4[it] = *(const float4*)(Ap[it] + (kt + 1) * 32);
                bR4[it] = *(const float4*)(Bp[it] + (size_t)(kt + 1) * 32 * ldb);
            }
        }
#pragma unroll
        for (int ks = 0; ks < 4; ks++) {
            int kb = ks * 8 + t;
            unsigned bh[4][2];
#pragma unroll
            for (int j = 0; j < 4; j++) {
                int n = warp_n * 32 + j * 8 + g;
                bh[j][0] = BsH[kb * 132 + n];
                bh[j][1] = BsH[(kb + 4) * 132 + n];
            }
#pragma unroll
            for (int i = 0; i < 4; i++) {
                int m = warp_m * 64 + i * 16 + g;
                unsigned ah[4];
                ah[0] = AsH[m * 36 + kb];
                ah[1] = AsH[(m + 8) * 36 + kb];
                ah[2] = AsH[m * 36 + kb + 4];
                ah[3] = AsH[(m + 8) * 36 + kb + 4];
#pragma unroll
                for (int j = 0; j < 4; j++)
                    MMA_TF32(acc[i][j], ah, bh[j]);
            }
        }
        __syncthreads();
    }

#pragma unroll
    for (int i = 0; i < 4; i++) {
#pragma unroll
        for (int j = 0; j < 4; j++) {
            int r0 = bm + warp_m * 64 + i * 16 + g;
            int c0 = bn + warp_n * 32 + j * 8 + 2 * t;
            if (r0 < M)
                *(float2*)&C[(size_t)r0 * ldc + c0] =
                    make_float2(alpha * acc[i][j][0], alpha * acc[i][j][1]);
            if (r0 + 8 < M)
                *(float2*)&C[(size_t)(r0 + 8) * ldc + c0] =
                    make_float2(alpha * acc[i][j][2], alpha * acc[i][j][3]);
        }
    }
}

// ---------------- single-tf32 batched NT GEMM for m (bf16 out) ---------------
__global__ void __launch_bounds__(256, 2)
gemm_m_tf32(const float* __restrict__ q2, const float* __restrict__ Wpkv,
            __nv_bfloat16* __restrict__ mOut)
{
    extern __shared__ unsigned smu[];
    unsigned* As = smu;              // [128][36]
    unsigned* Bs = smu + 4608;       // [128n][36]

    int h = blockIdx.z;
    const float* A  = q2   + h * 64;                  // lda 768
    const float* BT = Wpkv + h * 64;                  // ld 1536
    __nv_bfloat16* Cb = mOut + h * 768;               // ldc 9216

    int tid = threadIdx.x;
    int lane = tid & 31, wid = tid >> 5;
    int warp_m = wid >> 2, warp_n = wid & 3;
    int g = lane >> 2, t = lane & 3;
    int bm = blockIdx.y * 128, bn = blockIdx.x * 128;

    int r0t = tid >> 3, c0t = (tid & 7) << 2;

    float4 aPre[4], bPre[4];
#pragma unroll
    for (int it = 0; it < 4; it++) {
        int aR2 = bm + r0t + it * 32; if (aR2 >= M1) aR2 = M1 - 1;
        aPre[it] = *(const float4*)(A + (size_t)aR2 * 768 + c0t);
        bPre[it] = *(const float4*)(BT + (size_t)(bn + r0t + it * 32) * 1536 + c0t);
    }

    float acc[4][4][4] = {};
#pragma unroll 1
    for (int kt = 0; kt < 2; kt++) {                  // K = 64 = 2 x 32
#pragma unroll
        for (int it = 0; it < 4; it++) {
            int r = r0t + it * 32;
            *(uint4*)&As[r * 36 + c0t] = cvt_tf4(aPre[it]);
            *(uint4*)&Bs[r * 36 + c0t] = cvt_tf4(bPre[it]);
        }
        __syncthreads();
        if (kt == 0) {
#pragma unroll
            for (int it = 0; it < 4; it++) {
                int aR2 = bm + r0t + it * 32; if (aR2 >= M1) aR2 = M1 - 1;
                aPre[it] = *(const float4*)(A + (size_t)aR2 * 768 + 32 + c0t);
                bPre[it] = *(const float4*)(BT + (size_t)(bn + r0t + it * 32) * 1536 + 32 + c0t);
            }
        }
#pragma unroll
        for (int ks = 0; ks < 4; ks++) {
            int kb = ks * 8 + t;
            unsigned bh[4][2];
#pragma unroll
            for (int j = 0; j < 4; j++) {
                int n = warp_n * 32 + j * 8 + g;
                bh[j][0] = Bs[n * 36 + kb];
                bh[j][1] = Bs[n * 36 + kb + 4];
            }
#pragma unroll
            for (int i = 0; i < 4; i++) {
                int m = warp_m * 64 + i * 16 + g;
                unsigned ah[4];
                ah[0] = As[m * 36 + kb];
                ah[1] = As[(m + 8) * 36 + kb];
                ah[2] = As[m * 36 + kb + 4];
                ah[3] = As[(m + 8) * 36 + kb + 4];
#pragma unroll
                for (int j = 0; j < 4; j++)
                    MMA_TF32(acc[i][j], ah, bh[j]);
            }
        }
        __syncthreads();
    }

#pragma unroll
    for (int i = 0; i < 4; i++) {
#pragma unroll
        for (int j = 0; j < 4; j++) {
            int r0 = bm + warp_m * 64 + i * 16 + g;
            int c0 = bn + warp_n * 32 + j * 8 + 2 * t;
            __nv_bfloat162 v0, v1;
            v0.x = __float2bfloat16(acc[i][j][0]);
            v0.y = __float2bfloat16(acc[i][j][1]);
            v1.x = __float2bfloat16(acc[i][j][2]);
            v1.y = __float2bfloat16(acc[i][j][3]);
            if (r0 < M1)
                *(__nv_bfloat162*)&Cb[(size_t)r0 * 9216 + c0] = v0;
            if (r0 + 8 < M1)
                *(__nv_bfloat162*)&Cb[(size_t)(r0 + 8) * 9216 + c0] = v1;
        }
    }
}

// ---------------- stage-1 fused attention, tensor-core version ---------------
// Phase A: QsH 0 (128*68) | QsL 8704 | KsH 17408 (224*68) | KsL 32640  (47872 w)
// Phase B: Ps 0 (128*204=26112) | Vs 29184 (64*204=13056)
// red 47872 (512) | sxs 48384 (128)
__global__ void stage1_tf32(const float* __restrict__ qmat, const float* __restrict__ kv,
                            float* __restrict__ scores_out, float* __restrict__ x_out,
                            float* __restrict__ xpart)
{
    extern __shared__ unsigned smu[];
    unsigned* QsH = smu;
    unsigned* QsL = smu + 8704;
    unsigned* KsH = smu + 17408;
    unsigned* KsL = smu + 32640;
    unsigned* Ps  = smu;
    unsigned* Vs  = smu + 29184;
    float* red    = (float*)(smu + 47872);
    float* sxs    = (float*)(smu + 48384);

    int tid = threadIdx.x;
    int lane = tid & 31, wid = tid >> 5;
    int warp_m = wid >> 2, warp_n = wid & 3;   // 2m x 4n
    int g = lane >> 2, t = lane & 3;

    int q0  = blockIdx.x * 128;
    int f   = blockIdx.y;
    int bhz = blockIdx.z;
    int b = bhz / HH, h = bhz % HH;

    // ---- load Q (hi/lo tf32) ----
    const float* qbase = qmat + (size_t)(b * QQ) * CC + h * 64;
#pragma unroll
    for (int it = 0; it < 8; it++) {
        int idx = tid + it * 256;
        int row = idx >> 4, c4 = (idx & 15) << 2;
        int qg = q0 + row; if (qg >= QQ) qg = QQ - 1;
        float4 v = *(const float4*)(qbase + (size_t)qg * CC + c4);
        uint4 hh, ll; cvt_hilo4(v, hh, ll);
        *(uint4*)&QsH[row * 68 + c4] = hh;
        *(uint4*)&QsL[row * 68 + c4] = ll;
    }
    // ---- load K (hi/lo tf32), zero pad rows 196..223 ----
    const float* kbase = kv + (size_t)(b * QQ + f * SS) * (2 * CC) + h * 64;
#pragma unroll
    for (int it = 0; it < 14; it++) {
        int idx = tid + it * 256;
        int s = idx >> 4, c4 = (idx & 15) << 2;
        float4 v = make_float4(0.f, 0.f, 0.f, 0.f);
        if (s < SS) v = *(const float4*)(kbase + (size_t)s * (2 * CC) + c4);
        uint4 hh, ll; cvt_hilo4(v, hh, ll);
        *(uint4*)&KsH[s * 68 + c4] = hh;
        *(uint4*)&KsL[s * 68 + c4] = ll;
    }
    __syncthreads();

    // ---- QK^T mma: warp tile 64m x 56n, K=64 in 8 steps, 3 terms ----
    float acc[4][7][4] = {};
#pragma unroll 1
    for (int ks = 0; ks < 8; ks++) {
        int kb = ks * 8 + t;
        unsigned bh[7][2], bl[7][2];
#pragma unroll
        for (int j = 0; j < 7; j++) {
            int n = (warp_n * 7 + j) * 8 + g;
            bh[j][0] = KsH[n * 68 + kb];
            bh[j][1] = KsH[n * 68 + kb + 4];
            bl[j][0] = KsL[n * 68 + kb];
            bl[j][1] = KsL[n * 68 + kb + 4];
        }
#pragma unroll
        for (int i = 0; i < 4; i++) {
            int m = warp_m * 64 + i * 16 + g;
            unsigned ah[4], al[4];
            ah[0] = QsH[m * 68 + kb];
            ah[1] = QsH[(m + 8) * 68 + kb];
            ah[2] = QsH[m * 68 + kb + 4];
            ah[3] = QsH[(m + 8) * 68 + kb + 4];
            al[0] = QsL[m * 68 + kb];
            al[1] = QsL[(m + 8) * 68 + kb];
            al[2] = QsL[m * 68 + kb + 4];
            al[3] = QsL[(m + 8) * 68 + kb + 4];
#pragma unroll
            for (int j = 0; j < 7; j++) {
                MMA_TF32(acc[i][j], ah, bh[j]);
                MMA_TF32(acc[i][j], ah, bl[j]);
                MMA_TF32(acc[i][j], al, bh[j]);
            }
        }
    }
    __syncthreads();   // Q/K smem dead; phase B regions may now be written

    // ---- load V transposed to Vs[d][s] (single tf32), rows padded to 200 ----
    const float* vbase = kbase + CC;
#pragma unroll
    for (int it = 0; it < 13; it++) {
        int idx = tid + it * 256;
        if (idx < 64 * 50) {
            int d = idx & 63, sg = idx >> 6;   // sg 0..49
            int s0 = sg * 4;
            uint4 w;
            w.x = (s0 + 0 < SS) ? f2tf(vbase[(size_t)(s0 + 0) * (2 * CC) + d]) : 0u;
            w.y = (s0 + 1 < SS) ? f2tf(vbase[(size_t)(s0 + 1) * (2 * CC) + d]) : 0u;
            w.z = (s0 + 2 < SS) ? f2tf(vbase[(size_t)(s0 + 2) * (2 * CC) + d]) : 0u;
            w.w = (s0 + 3 < SS) ? f2tf(vbase[(size_t)(s0 + 3) * (2 * CC) + d]) : 0u;
            *(uint4*)&Vs[d * PST + s0] = w;
        }
    }

    // ---- scale + write raw scores ----
    const float scale = 0.125f;
#pragma unroll
    for (int i = 0; i < 4; i++) {
        int r0 = warp_m * 64 + i * 16 + g;
#pragma unroll
        for (int j = 0; j < 7; j++) {
            int col = (warp_n * 7 + j) * 8 + 2 * t;
#pragma unroll
            for (int c = 0; c < 4; c++) acc[i][j][c] *= scale;
            if (col < SS) {
                int qa = q0 + r0;
                if (qa < QQ) {
                    size_t bp = ((size_t)bhz * QQ + qa) * (FF * SS) + (size_t)f * SS + col;
                    *(float2*)&scores_out[bp] = make_float2(acc[i][j][0], acc[i][j][1]);
                }
                int qb2 = q0 + r0 + 8;
                if (qb2 < QQ) {
                    size_t bp = ((size_t)bhz * QQ + qb2) * (FF * SS) + (size_t)f * SS + col;
                    *(float2*)&scores_out[bp] = make_float2(acc[i][j][2], acc[i][j][3]);
                }
            }
        }
    }

    // ---- softmax over s (row-wise) ----
    float mxa[4], mxb[4];
#pragma unroll
    for (int i = 0; i < 4; i++) {
        float m0 = -1e30f, m1 = -1e30f;
#pragma unroll
        for (int j = 0; j < 7; j++) {
            int col = (warp_n * 7 + j) * 8 + 2 * t;
            if (col < SS) {
                m0 = fmaxf(m0, fmaxf(acc[i][j][0], acc[i][j][1]));
                m1 = fmaxf(m1, fmaxf(acc[i][j][2], acc[i][j][3]));
            }
        }
        m0 = fmaxf(m0, __shfl_xor_sync(0xffffffffu, m0, 1));
        m0 = fmaxf(m0, __shfl_xor_sync(0xffffffffu, m0, 2));
        m1 = fmaxf(m1, __shfl_xor_sync(0xffffffffu, m1, 1));
        m1 = fmaxf(m1, __shfl_xor_sync(0xffffffffu, m1, 2));
        int r0 = warp_m * 64 + i * 16 + g;
        if (t == 0) {
            red[r0 * 4 + warp_n] = m0;
            red[(r0 + 8) * 4 + warp_n] = m1;
        }
    }
    __syncthreads();
#pragma unroll
    for (int i = 0; i < 4; i++) {
        int r0 = warp_m * 64 + i * 16 + g;
        mxa[i] = fmaxf(fmaxf(red[r0 * 4], red[r0 * 4 + 1]),
                       fmaxf(red[r0 * 4 + 2], red[r0 * 4 + 3]));
        mxb[i] = fmaxf(fmaxf(red[(r0 + 8) * 4], red[(r0 + 8) * 4 + 1]),
                       fmaxf(red[(r0 + 8) * 4 + 2], red[(r0 + 8) * 4 + 3]));
    }
    __syncthreads();
#pragma unroll
    for (int i = 0; i < 4; i++) {
        float s0 = 0.f, s1 = 0.f;
#pragma unroll
        for (int j = 0; j < 7; j++) {
            int col = (warp_n * 7 + j) * 8 + 2 * t;
            if (col < SS) {
                acc[i][j][0] = __expf(acc[i][j][0] - mxa[i]);
                acc[i][j][1] = __expf(acc[i][j][1] - mxa[i]);
                acc[i][j][2] = __expf(acc[i][j][2] - mxb[i]);
                acc[i][j][3] = __expf(acc[i][j][3] - mxb[i]);
                s0 += acc[i][j][0] + acc[i][j][1];
                s1 += acc[i][j][2] + acc[i][j][3];
            } else {
                acc[i][j][0] = acc[i][j][1] = acc[i][j][2] = acc[i][j][3] = 0.f;
            }
        }
        s0 += __shfl_xor_sync(0xffffffffu, s0, 1);
        s0 += __shfl_xor_sync(0xffffffffu, s0, 2);
        s1 += __shfl_xor_sync(0xffffffffu, s1, 1);
        s1 += __shfl_xor_sync(0xffffffffu, s1, 2);
        int r0 = warp_m * 64 + i * 16 + g;
        if (t == 0) {
            red[r0 * 4 + warp_n] = s0;
            red[(r0 + 8) * 4 + warp_n] = s1;
        }
    }
    __syncthreads();
#pragma unroll
    for (int i = 0; i < 4; i++) {
        int r0 = warp_m * 64 + i * 16 + g;
        float inva = 1.0f / (red[r0 * 4] + red[r0 * 4 + 1] + red[r0 * 4 + 2] + red[r0 * 4 + 3]);
        float invb = 1.0f / (red[(r0 + 8) * 4] + red[(r0 + 8) * 4 + 1] +
                             red[(r0 + 8) * 4 + 2] + red[(r0 + 8) * 4 + 3]);
#pragma unroll
        for (int j = 0; j < 7; j++) {
            int col = (warp_n * 7 + j) * 8 + 2 * t;
            if (col < PVK) {   // Ps has only 200 columns
                Ps[r0 * PST + col]           = f2tf(acc[i][j][0] * inva);
                Ps[r0 * PST + col + 1]       = f2tf(acc[i][j][1] * inva);
                Ps[(r0 + 8) * PST + col]     = f2tf(acc[i][j][2] * invb);
                Ps[(r0 + 8) * PST + col + 1] = f2tf(acc[i][j][3] * invb);
            }
        }
    }
    __syncthreads();

    // ---- x = P @ V: warp tile 64m x 16n, K=200 in 25 steps, single term ----
    float xacc[4][2][4] = {};
#pragma unroll 1
    for (int ks = 0; ks < 25; ks++) {
        int kb = ks * 8 + t;
        unsigned bf[2][2];
#pragma unroll
        for (int j = 0; j < 2; j++) {
            int n = warp_n * 16 + j * 8 + g;
            bf[j][0] = Vs[n * PST + kb];
            bf[j][1] = Vs[n * PST + kb + 4];
        }
#pragma unroll
        for (int i = 0; i < 4; i++) {
            int m = warp_m * 64 + i * 16 + g;
            unsigned a[4];
            a[0] = Ps[m * PST + kb];
            a[1] = Ps[(m + 8) * PST + kb];
            a[2] = Ps[m * PST + kb + 4];
            a[3] = Ps[(m + 8) * PST + kb + 4];
#pragma unroll
            for (int j = 0; j < 2; j++)
                MMA_TF32(xacc[i][j], a, bf[j]);
        }
    }

    // ---- write x + fp32 column sums over this q-tile ----
    float cs[2][2] = {};
#pragma unroll
    for (int i = 0; i < 4; i++) {
        int r0 = warp_m * 64 + i * 16 + g;
        bool va = (q0 + r0) < QQ;
        bool vb = (q0 + r0 + 8) < QQ;
#pragma unroll
        for (int j = 0; j < 2; j++) {
            int c = h * 64 + warp_n * 16 + j * 8 + 2 * t;
            if (va) {
                *(float2*)&x_out[((size_t)(b * QQ + q0 + r0) * FF + f) * CC + c] =
                    make_float2(xacc[i][j][0], xacc[i][j][1]);
                cs[j][0] += xacc[i][j][0];
                cs[j][1] += xacc[i][j][1];
            }
            if (vb) {
                *(float2*)&x_out[((size_t)(b * QQ + q0 + r0 + 8) * FF + f) * CC + c] =
                    make_float2(xacc[i][j][2], xacc[i][j][3]);
                cs[j][0] += xacc[i][j][2];
                cs[j][1] += xacc[i][j][3];
            }
        }
    }
#pragma unroll
    for (int off = 4; off < 32; off <<= 1) {
#pragma unroll
        for (int j = 0; j < 2; j++) {
            cs[j][0] += __shfl_down_sync(0xffffffffu, cs[j][0], off);
            cs[j][1] += __shfl_down_sync(0xffffffffu, cs[j][1], off);
        }
    }
    if (lane < 4) {
#pragma unroll
        for (int j = 0; j < 2; j++) {
            sxs[warp_m * 64 + warp_n * 16 + j * 8 + 2 * t]     = cs[j][0];
            sxs[warp_m * 64 + warp_n * 16 + j * 8 + 2 * t + 1] = cs[j][1];
        }
    }
    __syncthreads();
    if (tid < 64) {
        float tot = sxs[tid] + sxs[64 + tid];
        xpart[(((size_t)blockIdx.x * BB + b) * FF + f) * CC + h * 64 + tid] = tot;
    }
}

// ---------------- final xsum over 13 q-tiles ---------------------------------
__global__ void xsum_final13(const float* __restrict__ part, float* __restrict__ xsum)
{
    int c = blockIdx.x * 256 + threadIdx.x;
    int f = blockIdx.y;
    int b = blockIdx.z;
    float acc = 0.f;
#pragma unroll
    for (int qt = 0; qt < QTILES; qt++)
        acc += part[(((size_t)qt * BB + b) * FF + f) * CC + c];
    xsum[((size_t)b * FF + f) * CC + c] = acc;
}

// ---------------- V2sum = Xsum @ Wpkv_v  (tiny) ------------------------------
__global__ void v2_kernel(const float* __restrict__ xsum, const float* __restrict__ Wpkv,
                          float* __restrict__ v2)
{
    __shared__ float xs[CC];
    int bf = blockIdx.x;
    int tid = threadIdx.x;
    for (int i = tid; i < CC; i += 256) xs[i] = xsum[(size_t)bf * CC + i];
    __syncthreads();
#pragma unroll
    for (int r = 0; r < 3; r++) {
        int co = r * 256 + tid;
        float acc = 0.f;
        for (int ci = 0; ci < CC; ci++)
            acc += xs[ci] * Wpkv[(size_t)ci * (2 * CC) + CC + co];
        v2[(size_t)bf * CC + co] = acc;
    }
}

// ---------------- stage-2: attn2 softmax + y (m in bf16) --------------------
__global__ void stage2_kernel(const float* __restrict__ x, const __nv_bfloat16* __restrict__ m,
                              const float* __restrict__ v2, float* __restrict__ y)
{
    __shared__ float xs[FF * CC];
    int bq = blockIdx.x;
    int b = bq / QQ;
    int tid = threadIdx.x;

    const float* xrow = x + (size_t)bq * (FF * CC);
    for (int idx = tid; idx < (FF * CC) / 4; idx += 384)
        *(float4*)&xs[idx << 2] = *(const float4*)(xrow + ((size_t)idx << 2));
    __syncthreads();

    int h = tid >> 5, lane = tid & 31;
    const __nv_bfloat16* mrow = m + (size_t)bq * (HH * CC) + (size_t)h * CC;

    float a[FF];
#pragma unroll
    for (int f2 = 0; f2 < FF; f2++) a[f2] = 0.f;
#pragma unroll 4
    for (int c = lane; c < CC; c += 32) {
        float mv = __bfloat162float(__ldg(mrow + c));
#pragma unroll
        for (int f2 = 0; f2 < FF; f2++) a[f2] += mv * xs[f2 * CC + c];
    }
#pragma unroll
    for (int f2 = 0; f2 < FF; f2++)
        for (int o = 16; o > 0; o >>= 1) a[f2] += __shfl_xor_sync(0xffffffffu, a[f2], o);

    float mx = a[0];
#pragma unroll
    for (int f2 = 1; f2 < FF; f2++) mx = fmaxf(mx, a[f2]);
    float ssum = 0.f;
#pragma unroll
    for (int f2 = 0; f2 < FF; f2++) { a[f2] = __expf(a[f2] - mx); ssum += a[f2]; }
    float inv = 1.0f / ssum;
#pragma unroll
    for (int f2 = 0; f2 < FF; f2++) a[f2] *= inv;

    for (int dd = lane; dd < 64; dd += 32) {
        float acc = 0.f;
#pragma unroll
        for (int f2 = 0; f2 < FF; f2++)
            acc += a[f2] * __ldg(v2 + ((size_t)(b * FF + f2)) * CC + h * 64 + dd);
        y[(size_t)bq * CC + h * 64 + dd] = acc;
    }
}

// ---------------- launch -----------------------------------------------------
extern "C" void kernel_launch(void* const* d_in, const int* in_sizes, int n_in,
                              void* d_out, int out_size)
{
    const float* query  = (const float*)d_in[0];
    const float* memory = (const float*)d_in[1];
    const float* Wq     = (const float*)d_in[2];
    const float* Wkv    = (const float*)d_in[3];
    const float* Wpq    = (const float*)d_in[4];
    const float* Wpkv   = (const float*)d_in[5];
    const float* Wproj  = (const float*)d_in[6];
    const float* bproj  = (const float*)d_in[7];

    float* out        = (float*)d_out;
    float* out_scores = out + QOUT_ELEMS;

    float *qp, *kvp, *q2p, *xp, *xp2p, *xsump, *v2p, *yp;
    __nv_bfloat16* mp;
    cudaGetSymbolAddress((void**)&qp,    g_q);
    cudaGetSymbolAddress((void**)&kvp,   g_kv);
    cudaGetSymbolAddress((void**)&q2p,   g_q2);
    cudaGetSymbolAddress((void**)&mp,    g_m);
    cudaGetSymbolAddress((void**)&xp,    g_x);
    cudaGetSymbolAddress((void**)&xp2p,  g_xp2);
    cudaGetSymbolAddress((void**)&xsump, g_xsum);
    cudaGetSymbolAddress((void**)&v2p,   g_v2);
    cudaGetSymbolAddress((void**)&yp,    g_y);

    const int NN_SMEM  = (4608 * 2 + 4224 * 2) * 4;   // 70656
    const int NN1_SMEM = (4608 + 4224) * 4;           // 35328
    const int NT_SMEM  = (4608 * 2) * 4;              // 36864
    const int S1_SMEM  = 48512 * 4;                   // 194048
    cudaFuncSetAttribute(sgemm_tf32_nn,    cudaFuncAttributeMaxDynamicSharedMemorySize, NN_SMEM);
    cudaFuncSetAttribute(sgemm_tf32_nn_1t, cudaFuncAttributeMaxDynamicSharedMemorySize, NN1_SMEM);
    cudaFuncSetAttribute(gemm_m_tf32,      cudaFuncAttributeMaxDynamicSharedMemorySize, NT_SMEM);
    cudaFuncSetAttribute(stage1_tf32,      cudaFuncAttributeMaxDynamicSharedMemorySize, S1_SMEM);

    const int MB = (M1 + 127) / 128;  // 25 row-blocks

    // 1. q = query @ Wq  (3-term: feeds scores)
    sgemm_tf32_nn<<<dim3(CC / 128, MB), 256, NN_SMEM>>>(query, Wq, qp, M1, CC, CC, CC, CC, 1.0f, nullptr);
    // 2. kv = memory @ Wkv  (3-term)
    sgemm_tf32_nn<<<dim3((2 * CC) / 128, MB), 256, NN_SMEM>>>(memory, Wkv, kvp, M1, CC, CC, 2 * CC, 2 * CC, 1.0f, nullptr);
    // 3. q2 = (q @ Wpq) * d^-0.5  (single-pass: feeds bf16 m)
    sgemm_tf32_nn_1t<<<dim3(CC / 128, MB), 256, NN1_SMEM>>>(qp, Wpq, q2p, M1, CC, CC, CC, CC, 0.125f);
    // 4. m (batched per-head NT, single tf32, bf16 out)
    gemm_m_tf32<<<dim3(CC / 128, MB, HH), 256, NT_SMEM>>>(q2p, Wpkv, mp);
    // 5. stage-1 attention: scores + x + fused per-tile xsum
    stage1_tf32<<<dim3(QTILES, FF, BB * HH), 256, S1_SMEM>>>(qp, kvp, out_scores, xp, xp2p);
    // 6. final xsum over q-tiles
    xsum_final13<<<dim3(CC / 256, FF, BB), 256>>>(xp2p, xsump);
    // 7. V2sum = Xsum @ Wpkv_v
    v2_kernel<<<BB * FF, 256>>>(xsump, Wpkv, v2p);
    // 8. stage-2 attention -> y
    stage2_kernel<<<M1, 384>>>(xp, mp, v2p, yp);
    // 9. q_out = y @ Wproj + bproj  (3-term: output)
    sgemm_tf32_nn<<<dim3(CC / 128, MB), 256, NN_SMEM>>>(yp, Wproj, out, M1, CC, CC, CC, CC, 1.0f, bproj);
}

// round 16
// speedup vs baseline: 1.0902x; 1.0452x over previous
#include <cuda_runtime.h>
#include <cuda_bf16.h>
#include <math.h>
#include <stdint.h>

// Problem constants (fixed shapes)
#define BB 2
#define QQ 1568
#define CC 768
#define HH 12
#define DD 64
#define FF 8
#define SS 196
#define M1 (BB*QQ)              // 3136 flattened rows
#define QOUT_ELEMS (BB*QQ*CC)   // 2408448
#define QTILES 13               // ceil(1568/128)
#define PVK 200                 // PV padded K (196 -> 200)
#define PST 204                 // Ps/Vs row stride (words), 204 mod 32 = 12 (conflict-free)

// ---------------- scratch (device globals: allocation-free rule) -------------
__device__ float          g_q    [M1*CC];
__device__ float          g_kv   [M1*2*CC];
__device__ float          g_q2   [M1*CC];
__device__ __nv_bfloat16  g_m    [M1*HH*CC];
__device__ float          g_x    [BB*QQ*FF*CC];
__device__ float          g_xp2  [QTILES*BB*FF*CC];
__device__ float          g_v2   [BB*FF*CC];
__device__ float          g_y    [M1*CC];

namespace {
struct ModulePreload {
    ModulePreload() {
        void* p = nullptr;
        cudaGetSymbolAddress(&p, g_q);
    }
};
static ModulePreload _module_preload;
}

// ---------------- tf32 helpers ----------------------------------------------
__device__ __forceinline__ unsigned f2tf(float x) {
    unsigned r;
    asm("cvt.rna.tf32.f32 %0, %1;" : "=r"(r) : "f"(x));
    return r;
}
__device__ __forceinline__ void cvt_hilo4(float4 v, uint4& h, uint4& l) {
    h.x = f2tf(v.x); h.y = f2tf(v.y); h.z = f2tf(v.z); h.w = f2tf(v.w);
    l.x = f2tf(v.x - __uint_as_float(h.x));
    l.y = f2tf(v.y - __uint_as_float(h.y));
    l.z = f2tf(v.z - __uint_as_float(h.z));
    l.w = f2tf(v.w - __uint_as_float(h.w));
}
__device__ __forceinline__ uint4 cvt_tf4(float4 v) {
    uint4 h;
    h.x = f2tf(v.x); h.y = f2tf(v.y); h.z = f2tf(v.z); h.w = f2tf(v.w);
    return h;
}
#define MMA_TF32(d, a, b)                                                     \
    asm volatile(                                                             \
        "mma.sync.aligned.m16n8k8.row.col.f32.tf32.tf32.f32 "                 \
        "{%0,%1,%2,%3}, {%4,%5,%6,%7}, {%8,%9}, {%0,%1,%2,%3};"               \
        : "+f"((d)[0]), "+f"((d)[1]), "+f"((d)[2]), "+f"((d)[3])              \
        : "r"((a)[0]), "r"((a)[1]), "r"((a)[2]), "r"((a)[3]),                 \
          "r"((b)[0]), "r"((b)[1]))

// ---------------- split-tf32 128x128 GEMM (NN), register-prefetch -----------
__global__ void sgemm_tf32_nn(const float* __restrict__ A, const float* __restrict__ B,
                              float* __restrict__ C, int M, int K,
                              int lda, int ldb, int ldc,
                              float alpha, const float* __restrict__ bias)
{
    extern __shared__ unsigned smu[];
    unsigned* AsH = smu;             // [128][36]
    unsigned* AsL = AsH + 4608;
    unsigned* BsH = AsL + 4608;      // [32][132]
    unsigned* BsL = BsH + 4224;

    int tid = threadIdx.x;
    int lane = tid & 31, wid = tid >> 5;
    int warp_m = wid >> 2, warp_n = wid & 3;
    int g = lane >> 2, t = lane & 3;
    int bm = blockIdx.y * 128, bn = blockIdx.x * 128;

    const float* Ap[4];
    const float* Bp[4];
    int aoff[4], boff[4];
#pragma unroll
    for (int it = 0; it < 4; it++) {
        int idx = tid + it * 256;
        int ar = idx >> 3, ac = (idx & 7) << 2;
        int aR = bm + ar; if (aR >= M) aR = M - 1;
        Ap[it] = A + (size_t)aR * lda + ac;
        aoff[it] = ar * 36 + ac;
        int bk = idx >> 5, bn0 = (idx & 31) << 2;
        Bp[it] = B + (size_t)bk * ldb + bn + bn0;
        boff[it] = bk * 132 + bn0;
    }

    float4 aR4[4], bR4[4];
#pragma unroll
    for (int it = 0; it < 4; it++) {
        aR4[it] = *(const float4*)(Ap[it]);
        bR4[it] = *(const float4*)(Bp[it]);
    }

    float acc[4][4][4] = {};
    int nkt = K >> 5;
    for (int kt = 0; kt < nkt; kt++) {
#pragma unroll
        for (int it = 0; it < 4; it++) {
            uint4 h, l;
            cvt_hilo4(aR4[it], h, l);
            *(uint4*)&AsH[aoff[it]] = h;
            *(uint4*)&AsL[aoff[it]] = l;
            cvt_hilo4(bR4[it], h, l);
            *(uint4*)&BsH[boff[it]] = h;
            *(uint4*)&BsL[boff[it]] = l;
        }
        __syncthreads();
        if (kt + 1 < nkt) {
#pragma unroll
            for (int it = 0; it < 4; it++) {
                aR4[it] = *(const float4*)(Ap[it] + (kt + 1) * 32);
                bR4[it] = *(const float4*)(Bp[it] + (size_t)(kt + 1) * 32 * ldb);
            }
        }
#pragma unroll
        for (int ks = 0; ks < 4; ks++) {
            int kb = ks * 8 + t;
            unsigned bh[4][2], bl[4][2];
#pragma unroll
            for (int j = 0; j < 4; j++) {
                int n = warp_n * 32 + j * 8 + g;
                bh[j][0] = BsH[kb * 132 + n];
                bh[j][1] = BsH[(kb + 4) * 132 + n];
                bl[j][0] = BsL[kb * 132 + n];
                bl[j][1] = BsL[(kb + 4) * 132 + n];
            }
#pragma unroll
            for (int i = 0; i < 4; i++) {
                int m = warp_m * 64 + i * 16 + g;
                unsigned ah[4], al[4];
                ah[0] = AsH[m * 36 + kb];
                ah[1] = AsH[(m + 8) * 36 + kb];
                ah[2] = AsH[m * 36 + kb + 4];
                ah[3] = AsH[(m + 8) * 36 + kb + 4];
                al[0] = AsL[m * 36 + kb];
                al[1] = AsL[(m + 8) * 36 + kb];
                al[2] = AsL[m * 36 + kb + 4];
                al[3] = AsL[(m + 8) * 36 + kb + 4];
#pragma unroll
                for (int j = 0; j < 4; j++) {
                    MMA_TF32(acc[i][j], ah, bh[j]);
                    MMA_TF32(acc[i][j], ah, bl[j]);
                    MMA_TF32(acc[i][j], al, bh[j]);
                }
            }
        }
        __syncthreads();
    }

#pragma unroll
    for (int i = 0; i < 4; i++) {
#pragma unroll
        for (int j = 0; j < 4; j++) {
            int r0 = bm + warp_m * 64 + i * 16 + g;
            int c0 = bn + warp_n * 32 + j * 8 + 2 * t;
            float2 v0, v1;
            v0.x = alpha * acc[i][j][0]; v0.y = alpha * acc[i][j][1];
            v1.x = alpha * acc[i][j][2]; v1.y = alpha * acc[i][j][3];
            if (bias) {
                float bx = bias[c0], by = bias[c0 + 1];
                v0.x += bx; v0.y += by; v1.x += bx; v1.y += by;
            }
            if (r0 < M)     *(float2*)&C[(size_t)r0 * ldc + c0] = v0;
            if (r0 + 8 < M) *(float2*)&C[(size_t)(r0 + 8) * ldc + c0] = v1;
        }
    }
}

// ---------------- single-pass tf32 128x128 GEMM (NN) -------------------------
// For products whose consumer discards sub-tf32 precision (q2 -> bf16 m;
// V half of kv -> tf32 PV). Half smem, 1/3 mma.
__global__ void sgemm_tf32_nn_1t(const float* __restrict__ A, const float* __restrict__ B,
                                 float* __restrict__ C, int M, int K,
                                 int lda, int ldb, int ldc, float alpha)
{
    extern __shared__ unsigned smu[];
    unsigned* AsH = smu;             // [128][36]
    unsigned* BsH = smu + 4608;      // [32][132]

    int tid = threadIdx.x;
    int lane = tid & 31, wid = tid >> 5;
    int warp_m = wid >> 2, warp_n = wid & 3;
    int g = lane >> 2, t = lane & 3;
    int bm = blockIdx.y * 128, bn = blockIdx.x * 128;

    const float* Ap[4];
    const float* Bp[4];
    int aoff[4], boff[4];
#pragma unroll
    for (int it = 0; it < 4; it++) {
        int idx = tid + it * 256;
        int ar = idx >> 3, ac = (idx & 7) << 2;
        int aR = bm + ar; if (aR >= M) aR = M - 1;
        Ap[it] = A + (size_t)aR * lda + ac;
        aoff[it] = ar * 36 + ac;
        int bk = idx >> 5, bn0 = (idx & 31) << 2;
        Bp[it] = B + (size_t)bk * ldb + bn + bn0;
        boff[it] = bk * 132 + bn0;
    }

    float4 aR4[4], bR4[4];
#pragma unroll
    for (int it = 0; it < 4; it++) {
        aR4[it] = *(const float4*)(Ap[it]);
        bR4[it] = *(const float4*)(Bp[it]);
    }

    float acc[4][4][4] = {};
    int nkt = K >> 5;
    for (int kt = 0; kt < nkt; kt++) {
#pragma unroll
        for (int it = 0; it < 4; it++) {
            *(uint4*)&AsH[aoff[it]] = cvt_tf4(aR4[it]);
            *(uint4*)&BsH[boff[it]] = cvt_tf4(bR4[it]);
        }
        __syncthreads();
        if (kt + 1 < nkt) {
#pragma unroll
            for (int it = 0; it < 4; it++) {
                aR4[it] = *(const float4*)(Ap[it] + (kt + 1) * 32);
                bR4[it] = *(const float4*)(Bp[it] + (size_t)(kt + 1) * 32 * ldb);
            }
        }
#pragma unroll
        for (int ks = 0; ks < 4; ks++) {
            int kb = ks * 8 + t;
            unsigned bh[4][2];
#pragma unroll
            for (int j = 0; j < 4; j++) {
                int n = warp_n * 32 + j * 8 + g;
                bh[j][0] = BsH[kb * 132 + n];
                bh[j][1] = BsH[(kb + 4) * 132 + n];
            }
#pragma unroll
            for (int i = 0; i < 4; i++) {
                int m = warp_m * 64 + i * 16 + g;
                unsigned ah[4];
                ah[0] = AsH[m * 36 + kb];
                ah[1] = AsH[(m + 8) * 36 + kb];
                ah[2] = AsH[m * 36 + kb + 4];
                ah[3] = AsH[(m + 8) * 36 + kb + 4];
#pragma unroll
                for (int j = 0; j < 4; j++)
                    MMA_TF32(acc[i][j], ah, bh[j]);
            }
        }
        __syncthreads();
    }

#pragma unroll
    for (int i = 0; i < 4; i++) {
#pragma unroll
        for (int j = 0; j < 4; j++) {
            int r0 = bm + warp_m * 64 + i * 16 + g;
            int c0 = bn + warp_n * 32 + j * 8 + 2 * t;
            if (r0 < M)
                *(float2*)&C[(size_t)r0 * ldc + c0] =
                    make_float2(alpha * acc[i][j][0], alpha * acc[i][j][1]);
            if (r0 + 8 < M)
                *(float2*)&C[(size_t)(r0 + 8) * ldc + c0] =
                    make_float2(alpha * acc[i][j][2], alpha * acc[i][j][3]);
        }
    }
}

// ---------------- single-tf32 batched NT GEMM for m (bf16 out) ---------------
// Single K-phase: whole K=64 resident in smem, one sync, 8 uninterrupted steps.
__global__ void __launch_bounds__(256, 2)
gemm_m_tf32(const float* __restrict__ q2, const float* __restrict__ Wpkv,
            __nv_bfloat16* __restrict__ mOut)
{
    extern __shared__ unsigned smu[];
    unsigned* As = smu;              // [128][68]
    unsigned* Bs = smu + 8704;       // [128n][68]

    int h = blockIdx.z;
    const float* A  = q2   + h * 64;                  // lda 768
    const float* BT = Wpkv + h * 64;                  // ld 1536
    __nv_bfloat16* Cb = mOut + h * 768;               // ldc 9216

    int tid = threadIdx.x;
    int lane = tid & 31, wid = tid >> 5;
    int warp_m = wid >> 2, warp_n = wid & 3;
    int g = lane >> 2, t = lane & 3;
    int bm = blockIdx.y * 128, bn = blockIdx.x * 128;

    // load full 128x64 tiles of A and B
#pragma unroll
    for (int it = 0; it < 8; it++) {
        int idx = tid + it * 256;
        int r = idx >> 4, c4 = (idx & 15) << 2;
        int aR = bm + r; if (aR >= M1) aR = M1 - 1;
        float4 a4 = *(const float4*)(A + (size_t)aR * 768 + c4);
        *(uint4*)&As[r * 68 + c4] = cvt_tf4(a4);
        float4 b4 = *(const float4*)(BT + (size_t)(bn + r) * 1536 + c4);
        *(uint4*)&Bs[r * 68 + c4] = cvt_tf4(b4);
    }
    __syncthreads();

    float acc[4][4][4] = {};
#pragma unroll
    for (int ks = 0; ks < 8; ks++) {
        int kb = ks * 8 + t;
        unsigned bh[4][2];
#pragma unroll
        for (int j = 0; j < 4; j++) {
            int n = warp_n * 32 + j * 8 + g;
            bh[j][0] = Bs[n * 68 + kb];
            bh[j][1] = Bs[n * 68 + kb + 4];
        }
#pragma unroll
        for (int i = 0; i < 4; i++) {
            int m = warp_m * 64 + i * 16 + g;
            unsigned ah[4];
            ah[0] = As[m * 68 + kb];
            ah[1] = As[(m + 8) * 68 + kb];
            ah[2] = As[m * 68 + kb + 4];
            ah[3] = As[(m + 8) * 68 + kb + 4];
#pragma unroll
            for (int j = 0; j < 4; j++)
                MMA_TF32(acc[i][j], ah, bh[j]);
        }
    }

#pragma unroll
    for (int i = 0; i < 4; i++) {
#pragma unroll
        for (int j = 0; j < 4; j++) {
            int r0 = bm + warp_m * 64 + i * 16 + g;
            int c0 = bn + warp_n * 32 + j * 8 + 2 * t;
            __nv_bfloat162 v0, v1;
            v0.x = __float2bfloat16(acc[i][j][0]);
            v0.y = __float2bfloat16(acc[i][j][1]);
            v1.x = __float2bfloat16(acc[i][j][2]);
            v1.y = __float2bfloat16(acc[i][j][3]);
            if (r0 < M1)
                *(__nv_bfloat162*)&Cb[(size_t)r0 * 9216 + c0] = v0;
            if (r0 + 8 < M1)
                *(__nv_bfloat162*)&Cb[(size_t)(r0 + 8) * 9216 + c0] = v1;
        }
    }
}

// ---------------- stage-1 fused attention, tensor-core version ---------------
// Phase A: QsH 0 (128*68) | QsL 8704 | KsH 17408 (224*68) | KsL 32640  (47872 w)
// Phase B: Ps 0 (128*204=26112) | Vs 29184 (64*204=13056)
// red 47872 (512) | sxs 48384 (128)
__global__ void stage1_tf32(const float* __restrict__ qmat, const float* __restrict__ kv,
                            float* __restrict__ scores_out, float* __restrict__ x_out,
                            float* __restrict__ xpart)
{
    extern __shared__ unsigned smu[];
    unsigned* QsH = smu;
    unsigned* QsL = smu + 8704;
    unsigned* KsH = smu + 17408;
    unsigned* KsL = smu + 32640;
    unsigned* Ps  = smu;
    unsigned* Vs  = smu + 29184;
    float* red    = (float*)(smu + 47872);
    float* sxs    = (float*)(smu + 48384);

    int tid = threadIdx.x;
    int lane = tid & 31, wid = tid >> 5;
    int warp_m = wid >> 2, warp_n = wid & 3;   // 2m x 4n
    int g = lane >> 2, t = lane & 3;

    int q0  = blockIdx.x * 128;
    int f   = blockIdx.y;
    int bhz = blockIdx.z;
    int b = bhz / HH, h = bhz % HH;

    // ---- load Q (hi/lo tf32) ----
    const float* qbase = qmat + (size_t)(b * QQ) * CC + h * 64;
#pragma unroll
    for (int it = 0; it < 8; it++) {
        int idx = tid + it * 256;
        int row = idx >> 4, c4 = (idx & 15) << 2;
        int qg = q0 + row; if (qg >= QQ) qg = QQ - 1;
        float4 v = *(const float4*)(qbase + (size_t)qg * CC + c4);
        uint4 hh, ll; cvt_hilo4(v, hh, ll);
        *(uint4*)&QsH[row * 68 + c4] = hh;
        *(uint4*)&QsL[row * 68 + c4] = ll;
    }
    // ---- load K (hi/lo tf32), zero pad rows 196..223 ----
    const float* kbase = kv + (size_t)(b * QQ + f * SS) * (2 * CC) + h * 64;
#pragma unroll
    for (int it = 0; it < 14; it++) {
        int idx = tid + it * 256;
        int s = idx >> 4, c4 = (idx & 15) << 2;
        float4 v = make_float4(0.f, 0.f, 0.f, 0.f);
        if (s < SS) v = *(const float4*)(kbase + (size_t)s * (2 * CC) + c4);
        uint4 hh, ll; cvt_hilo4(v, hh, ll);
        *(uint4*)&KsH[s * 68 + c4] = hh;
        *(uint4*)&KsL[s * 68 + c4] = ll;
    }
    __syncthreads();

    // ---- QK^T mma: warp tile 64m x 56n, K=64 in 8 steps, 3 terms ----
    float acc[4][7][4] = {};
#pragma unroll 1
    for (int ks = 0; ks < 8; ks++) {
        int kb = ks * 8 + t;
        unsigned bh[7][2], bl[7][2];
#pragma unroll
        for (int j = 0; j < 7; j++) {
            int n = (warp_n * 7 + j) * 8 + g;
            bh[j][0] = KsH[n * 68 + kb];
            bh[j][1] = KsH[n * 68 + kb + 4];
            bl[j][0] = KsL[n * 68 + kb];
            bl[j][1] = KsL[n * 68 + kb + 4];
        }
#pragma unroll
        for (int i = 0; i < 4; i++) {
            int m = warp_m * 64 + i * 16 + g;
            unsigned ah[4], al[4];
            ah[0] = QsH[m * 68 + kb];
            ah[1] = QsH[(m + 8) * 68 + kb];
            ah[2] = QsH[m * 68 + kb + 4];
            ah[3] = QsH[(m + 8) * 68 + kb + 4];
            al[0] = QsL[m * 68 + kb];
            al[1] = QsL[(m + 8) * 68 + kb];
            al[2] = QsL[m * 68 + kb + 4];
            al[3] = QsL[(m + 8) * 68 + kb + 4];
#pragma unroll
            for (int j = 0; j < 7; j++) {
                MMA_TF32(acc[i][j], ah, bh[j]);
                MMA_TF32(acc[i][j], ah, bl[j]);
                MMA_TF32(acc[i][j], al, bh[j]);
            }
        }
    }
    __syncthreads();   // Q/K smem dead; phase B regions may now be written

    // ---- load V transposed to Vs[d][s] (single tf32), rows padded to 200 ----
    const float* vbase = kbase + CC;
#pragma unroll
    for (int it = 0; it < 13; it++) {
        int idx = tid + it * 256;
        if (idx < 64 * 50) {
            int d = idx & 63, sg = idx >> 6;   // sg 0..49
            int s0 = sg * 4;
            uint4 w;
            w.x = (s0 + 0 < SS) ? f2tf(vbase[(size_t)(s0 + 0) * (2 * CC) + d]) : 0u;
            w.y = (s0 + 1 < SS) ? f2tf(vbase[(size_t)(s0 + 1) * (2 * CC) + d]) : 0u;
            w.z = (s0 + 2 < SS) ? f2tf(vbase[(size_t)(s0 + 2) * (2 * CC) + d]) : 0u;
            w.w = (s0 + 3 < SS) ? f2tf(vbase[(size_t)(s0 + 3) * (2 * CC) + d]) : 0u;
            *(uint4*)&Vs[d * PST + s0] = w;
        }
    }

    // ---- scale + write raw scores ----
    const float scale = 0.125f;
#pragma unroll
    for (int i = 0; i < 4; i++) {
        int r0 = warp_m * 64 + i * 16 + g;
#pragma unroll
        for (int j = 0; j < 7; j++) {
            int col = (warp_n * 7 + j) * 8 + 2 * t;
#pragma unroll
            for (int c = 0; c < 4; c++) acc[i][j][c] *= scale;
            if (col < SS) {
                int qa = q0 + r0;
                if (qa < QQ) {
                    size_t bp = ((size_t)bhz * QQ + qa) * (FF * SS) + (size_t)f * SS + col;
                    *(float2*)&scores_out[bp] = make_float2(acc[i][j][0], acc[i][j][1]);
                }
                int qb2 = q0 + r0 + 8;
                if (qb2 < QQ) {
                    size_t bp = ((size_t)bhz * QQ + qb2) * (FF * SS) + (size_t)f * SS + col;
                    *(float2*)&scores_out[bp] = make_float2(acc[i][j][2], acc[i][j][3]);
                }
            }
        }
    }

    // ---- softmax over s (row-wise) ----
    float mxa[4], mxb[4];
#pragma unroll
    for (int i = 0; i < 4; i++) {
        float m0 = -1e30f, m1 = -1e30f;
#pragma unroll
        for (int j = 0; j < 7; j++) {
            int col = (warp_n * 7 + j) * 8 + 2 * t;
            if (col < SS) {
                m0 = fmaxf(m0, fmaxf(acc[i][j][0], acc[i][j][1]));
                m1 = fmaxf(m1, fmaxf(acc[i][j][2], acc[i][j][3]));
            }
        }
        m0 = fmaxf(m0, __shfl_xor_sync(0xffffffffu, m0, 1));
        m0 = fmaxf(m0, __shfl_xor_sync(0xffffffffu, m0, 2));
        m1 = fmaxf(m1, __shfl_xor_sync(0xffffffffu, m1, 1));
        m1 = fmaxf(m1, __shfl_xor_sync(0xffffffffu, m1, 2));
        int r0 = warp_m * 64 + i * 16 + g;
        if (t == 0) {
            red[r0 * 4 + warp_n] = m0;
            red[(r0 + 8) * 4 + warp_n] = m1;
        }
    }
    __syncthreads();
#pragma unroll
    for (int i = 0; i < 4; i++) {
        int r0 = warp_m * 64 + i * 16 + g;
        mxa[i] = fmaxf(fmaxf(red[r0 * 4], red[r0 * 4 + 1]),
                       fmaxf(red[r0 * 4 + 2], red[r0 * 4 + 3]));
        mxb[i] = fmaxf(fmaxf(red[(r0 + 8) * 4], red[(r0 + 8) * 4 + 1]),
                       fmaxf(red[(r0 + 8) * 4 + 2], red[(r0 + 8) * 4 + 3]));
    }
    __syncthreads();
#pragma unroll
    for (int i = 0; i < 4; i++) {
        float s0 = 0.f, s1 = 0.f;
#pragma unroll
        for (int j = 0; j < 7; j++) {
            int col = (warp_n * 7 + j) * 8 + 2 * t;
            if (col < SS) {
                acc[i][j][0] = __expf(acc[i][j][0] - mxa[i]);
                acc[i][j][1] = __expf(acc[i][j][1] - mxa[i]);
                acc[i][j][2] = __expf(acc[i][j][2] - mxb[i]);
                acc[i][j][3] = __expf(acc[i][j][3] - mxb[i]);
                s0 += acc[i][j][0] + acc[i][j][1];
                s1 += acc[i][j][2] + acc[i][j][3];
            } else {
                acc[i][j][0] = acc[i][j][1] = acc[i][j][2] = acc[i][j][3] = 0.f;
            }
        }
        s0 += __shfl_xor_sync(0xffffffffu, s0, 1);
        s0 += __shfl_xor_sync(0xffffffffu, s0, 2);
        s1 += __shfl_xor_sync(0xffffffffu, s1, 1);
        s1 += __shfl_xor_sync(0xffffffffu, s1, 2);
        int r0 = warp_m * 64 + i * 16 + g;
        if (t == 0) {
            red[r0 * 4 + warp_n] = s0;
            red[(r0 + 8) * 4 + warp_n] = s1;
        }
    }
    __syncthreads();
#pragma unroll
    for (int i = 0; i < 4; i++) {
        int r0 = warp_m * 64 + i * 16 + g;
        float inva = 1.0f / (red[r0 * 4] + red[r0 * 4 + 1] + red[r0 * 4 + 2] + red[r0 * 4 + 3]);
        float invb = 1.0f / (red[(r0 + 8) * 4] + red[(r0 + 8) * 4 + 1] +
                             red[(r0 + 8) * 4 + 2] + red[(r0 + 8) * 4 + 3]);
#pragma unroll
        for (int j = 0; j < 7; j++) {
            int col = (warp_n * 7 + j) * 8 + 2 * t;
            if (col < PVK) {   // Ps has only 200 columns
                Ps[r0 * PST + col]           = f2tf(acc[i][j][0] * inva);
                Ps[r0 * PST + col + 1]       = f2tf(acc[i][j][1] * inva);
                Ps[(r0 + 8) * PST + col]     = f2tf(acc[i][j][2] * invb);
                Ps[(r0 + 8) * PST + col + 1] = f2tf(acc[i][j][3] * invb);
            }
        }
    }
    __syncthreads();

    // ---- x = P @ V: warp tile 64m x 16n, K=200 in 25 steps, single term ----
    float xacc[4][2][4] = {};
#pragma unroll 1
    for (int ks = 0; ks < 25; ks++) {
        int kb = ks * 8 + t;
        unsigned bf[2][2];
#pragma unroll
        for (int j = 0; j < 2; j++) {
            int n = warp_n * 16 + j * 8 + g;
            bf[j][0] = Vs[n * PST + kb];
            bf[j][1] = Vs[n * PST + kb + 4];
        }
#pragma unroll
        for (int i = 0; i < 4; i++) {
            int m = warp_m * 64 + i * 16 + g;
            unsigned a[4];
            a[0] = Ps[m * PST + kb];
            a[1] = Ps[(m + 8) * PST + kb];
            a[2] = Ps[m * PST + kb + 4];
            a[3] = Ps[(m + 8) * PST + kb + 4];
#pragma unroll
            for (int j = 0; j < 2; j++)
                MMA_TF32(xacc[i][j], a, bf[j]);
        }
    }

    // ---- write x + fp32 column sums over this q-tile ----
    float cs[2][2] = {};
#pragma unroll
    for (int i = 0; i < 4; i++) {
        int r0 = warp_m * 64 + i * 16 + g;
        bool va = (q0 + r0) < QQ;
        bool vb = (q0 + r0 + 8) < QQ;
#pragma unroll
        for (int j = 0; j < 2; j++) {
            int c = h * 64 + warp_n * 16 + j * 8 + 2 * t;
            if (va) {
                *(float2*)&x_out[((size_t)(b * QQ + q0 + r0) * FF + f) * CC + c] =
                    make_float2(xacc[i][j][0], xacc[i][j][1]);
                cs[j][0] += xacc[i][j][0];
                cs[j][1] += xacc[i][j][1];
            }
            if (vb) {
                *(float2*)&x_out[((size_t)(b * QQ + q0 + r0 + 8) * FF + f) * CC + c] =
                    make_float2(xacc[i][j][2], xacc[i][j][3]);
                cs[j][0] += xacc[i][j][2];
                cs[j][1] += xacc[i][j][3];
            }
        }
    }
#pragma unroll
    for (int off = 4; off < 32; off <<= 1) {
#pragma unroll
        for (int j = 0; j < 2; j++) {
            cs[j][0] += __shfl_down_sync(0xffffffffu, cs[j][0], off);
            cs[j][1] += __shfl_down_sync(0xffffffffu, cs[j][1], off);
        }
    }
    if (lane < 4) {
#pragma unroll
        for (int j = 0; j < 2; j++) {
            sxs[warp_m * 64 + warp_n * 16 + j * 8 + 2 * t]     = cs[j][0];
            sxs[warp_m * 64 + warp_n * 16 + j * 8 + 2 * t + 1] = cs[j][1];
        }
    }
    __syncthreads();
    if (tid < 64) {
        float tot = sxs[tid] + sxs[64 + tid];
        xpart[(((size_t)blockIdx.x * BB + b) * FF + f) * CC + h * 64 + tid] = tot;
    }
}

// ---------------- V2sum: reduce per-qtile sums + GEMV (fused) ----------------
__global__ void v2_kernel(const float* __restrict__ part, const float* __restrict__ Wpkv,
                          float* __restrict__ v2)
{
    __shared__ float xs[CC];
    int bf = blockIdx.x;             // b*FF + f
    int b = bf / FF, f = bf % FF;
    int tid = threadIdx.x;
    for (int i = tid; i < CC; i += 256) {
        float acc = 0.f;
#pragma unroll
        for (int qt = 0; qt < QTILES; qt++)
            acc += part[(((size_t)qt * BB + b) * FF + f) * CC + i];
        xs[i] = acc;
    }
    __syncthreads();
#pragma unroll
    for (int r = 0; r < 3; r++) {
        int co = r * 256 + tid;
        float acc = 0.f;
        for (int ci = 0; ci < CC; ci++)
            acc += xs[ci] * Wpkv[(size_t)ci * (2 * CC) + CC + co];
        v2[(size_t)bf * CC + co] = acc;
    }
}

// ---------------- stage-2: attn2 softmax + y (m in bf16) --------------------
__global__ void stage2_kernel(const float* __restrict__ x, const __nv_bfloat16* __restrict__ m,
                              const float* __restrict__ v2, float* __restrict__ y)
{
    __shared__ float xs[FF * CC];
    int bq = blockIdx.x;
    int b = bq / QQ;
    int tid = threadIdx.x;

    const float* xrow = x + (size_t)bq * (FF * CC);
    for (int idx = tid; idx < (FF * CC) / 4; idx += 384)
        *(float4*)&xs[idx << 2] = *(const float4*)(xrow + ((size_t)idx << 2));
    __syncthreads();

    int h = tid >> 5, lane = tid & 31;
    const __nv_bfloat16* mrow = m + (size_t)bq * (HH * CC) + (size_t)h * CC;

    float a[FF];
#pragma unroll
    for (int f2 = 0; f2 < FF; f2++) a[f2] = 0.f;
#pragma unroll 4
    for (int c = lane; c < CC; c += 32) {
        float mv = __bfloat162float(__ldg(mrow + c));
#pragma unroll
        for (int f2 = 0; f2 < FF; f2++) a[f2] += mv * xs[f2 * CC + c];
    }
#pragma unroll
    for (int f2 = 0; f2 < FF; f2++)
        for (int o = 16; o > 0; o >>= 1) a[f2] += __shfl_xor_sync(0xffffffffu, a[f2], o);

    float mx = a[0];
#pragma unroll
    for (int f2 = 1; f2 < FF; f2++) mx = fmaxf(mx, a[f2]);
    float ssum = 0.f;
#pragma unroll
    for (int f2 = 0; f2 < FF; f2++) { a[f2] = __expf(a[f2] - mx); ssum += a[f2]; }
    float inv = 1.0f / ssum;
#pragma unroll
    for (int f2 = 0; f2 < FF; f2++) a[f2] *= inv;

    for (int dd = lane; dd < 64; dd += 32) {
        float acc = 0.f;
#pragma unroll
        for (int f2 = 0; f2 < FF; f2++)
            acc += a[f2] * __ldg(v2 + ((size_t)(b * FF + f2)) * CC + h * 64 + dd);
        y[(size_t)bq * CC + h * 64 + dd] = acc;
    }
}

// ---------------- launch -----------------------------------------------------
extern "C" void kernel_launch(void* const* d_in, const int* in_sizes, int n_in,
                              void* d_out, int out_size)
{
    const float* query  = (const float*)d_in[0];
    const float* memory = (const float*)d_in[1];
    const float* Wq     = (const float*)d_in[2];
    const float* Wkv    = (const float*)d_in[3];
    const float* Wpq    = (const float*)d_in[4];
    const float* Wpkv   = (const float*)d_in[5];
    const float* Wproj  = (const float*)d_in[6];
    const float* bproj  = (const float*)d_in[7];

    float* out        = (float*)d_out;
    float* out_scores = out + QOUT_ELEMS;

    float *qp, *kvp, *q2p, *xp, *xp2p, *v2p, *yp;
    __nv_bfloat16* mp;
    cudaGetSymbolAddress((void**)&qp,    g_q);
    cudaGetSymbolAddress((void**)&kvp,   g_kv);
    cudaGetSymbolAddress((void**)&q2p,   g_q2);
    cudaGetSymbolAddress((void**)&mp,    g_m);
    cudaGetSymbolAddress((void**)&xp,    g_x);
    cudaGetSymbolAddress((void**)&xp2p,  g_xp2);
    cudaGetSymbolAddress((void**)&v2p,   g_v2);
    cudaGetSymbolAddress((void**)&yp,    g_y);

    const int NN_SMEM  = (4608 * 2 + 4224 * 2) * 4;   // 70656
    const int NN1_SMEM = (4608 + 4224) * 4;           // 35328
    const int NT_SMEM  = (8704 * 2) * 4;              // 69632
    const int S1_SMEM  = 48512 * 4;                   // 194048
    cudaFuncSetAttribute(sgemm_tf32_nn,    cudaFuncAttributeMaxDynamicSharedMemorySize, NN_SMEM);
    cudaFuncSetAttribute(sgemm_tf32_nn_1t, cudaFuncAttributeMaxDynamicSharedMemorySize, NN1_SMEM);
    cudaFuncSetAttribute(gemm_m_tf32,      cudaFuncAttributeMaxDynamicSharedMemorySize, NT_SMEM);
    cudaFuncSetAttribute(stage1_tf32,      cudaFuncAttributeMaxDynamicSharedMemorySize, S1_SMEM);

    const int MB = (M1 + 127) / 128;  // 25 row-blocks

    // 1. q = query @ Wq  (3-term: feeds scores)
    sgemm_tf32_nn<<<dim3(CC / 128, MB), 256, NN_SMEM>>>(query, Wq, qp, M1, CC, CC, CC, CC, 1.0f, nullptr);
    // 2a. k = memory @ Wkv[:, :768]  (3-term: feeds scores)
    sgemm_tf32_nn<<<dim3(CC / 128, MB), 256, NN_SMEM>>>(memory, Wkv, kvp, M1, CC, CC, 2 * CC, 2 * CC, 1.0f, nullptr);
    // 2b. v = memory @ Wkv[:, 768:]  (single-pass: feeds tf32 PV)
    sgemm_tf32_nn_1t<<<dim3(CC / 128, MB), 256, NN1_SMEM>>>(memory, Wkv + CC, kvp + CC, M1, CC, CC, 2 * CC, 2 * CC, 1.0f);
    // 3. q2 = (q @ Wpq) * d^-0.5  (single-pass: feeds bf16 m)
    sgemm_tf32_nn_1t<<<dim3(CC / 128, MB), 256, NN1_SMEM>>>(qp, Wpq, q2p, M1, CC, CC, CC, CC, 0.125f);
    // 4. m (batched per-head NT, single tf32, single K-phase, bf16 out)
    gemm_m_tf32<<<dim3(CC / 128, MB, HH), 256, NT_SMEM>>>(q2p, Wpkv, mp);
    // 5. stage-1 attention: scores + x + fused per-tile xsum
    stage1_tf32<<<dim3(QTILES, FF, BB * HH), 256, S1_SMEM>>>(qp, kvp, out_scores, xp, xp2p);
    // 6. V2sum (fused qtile reduction + GEMV)
    v2_kernel<<<BB * FF, 256>>>(xp2p, Wpkv, v2p);
    // 7. stage-2 attention -> y
    stage2_kernel<<<M1, 384>>>(xp, mp, v2p, yp);
    // 8. q_out = y @ Wproj + bproj  (3-term: output)
    sgemm_tf32_nn<<<dim3(CC / 128, MB), 256, NN_SMEM>>>(yp, Wproj, out, M1, CC, CC, CC, CC, 1.0f, bproj);
}